// round 1
// baseline (speedup 1.0000x reference)
#include <cuda_runtime.h>
#include <cuda_bf16.h>
#include <math.h>

// Problem constants
#define BB 2
#define LL 2048
#define DD 1024
#define NQH 8
#define NKVH 2
#define HD 128
#define FFND 4096
#define ROWS (BB*LL)            // 4096
#define EPSV 1.1920929e-07f

// ---------------- scratch (device globals; no allocs allowed) ----------------
__device__ float g_h  [ROWS*DD];        // rmsnorm1 out
__device__ float g_q  [ROWS*NQH*HD];    // q proj
__device__ float g_k  [ROWS*NKVH*HD];   // k proj
__device__ float g_v  [ROWS*NKVH*HD];   // v proj
__device__ float g_ctx[ROWS*NQH*HD];    // attention out
__device__ float g_x1 [ROWS*DD];        // post-attn residual stream
__device__ float g_h2 [ROWS*DD];        // rmsnorm2 out
__device__ float g_g  [ROWS*FFND];      // gate proj (reused for silu*u)
__device__ float g_u  [ROWS*FFND];      // up proj

// ---------------- RMSNorm: one block per row, 256 threads, float4 ----------------
__global__ __launch_bounds__(256) void rmsnorm_kernel(
    const float* __restrict__ x, const float* __restrict__ w, float* __restrict__ out)
{
    int row = blockIdx.x;
    const float4* xr = (const float4*)(x + (size_t)row * DD);
    float4 v = xr[threadIdx.x];                     // 256 * 4 = 1024 = DD
    float s = v.x*v.x + v.y*v.y + v.z*v.z + v.w*v.w;
    #pragma unroll
    for (int off = 16; off; off >>= 1) s += __shfl_xor_sync(0xffffffffu, s, off);
    __shared__ float red[8];
    if ((threadIdx.x & 31) == 0) red[threadIdx.x >> 5] = s;
    __syncthreads();
    float tot = red[0]+red[1]+red[2]+red[3]+red[4]+red[5]+red[6]+red[7];
    float r = rsqrtf(tot * (1.0f/DD) + EPSV);
    const float4 wv = ((const float4*)w)[threadIdx.x];
    float4 o = make_float4(v.x*r*wv.x, v.y*r*wv.y, v.z*r*wv.z, v.w*r*wv.w);
    ((float4*)(out + (size_t)row * DD))[threadIdx.x] = o;
}

// ---------------- RoPE (in-place): one thread per (token,head,d<64) ----------------
__global__ void rope_kernel(float* __restrict__ x, int H, int total)
{
    int idx = blockIdx.x * blockDim.x + threadIdx.x;
    if (idx >= total) return;
    int d = idx & 63;
    int t = idx >> 6;                 // (b*L + l)*H + h
    int pos = (t / H) & (LL - 1);     // l
    float freq = powf(10000.0f, (float)d * (2.0f / HD));
    float rad = (float)pos / freq;
    float sn, cs;
    sincosf(rad, &sn, &cs);
    float* p = x + (size_t)t * HD;
    float x1 = p[d], x2 = p[d + 64];
    p[d]      = x1*cs - x2*sn;
    p[d + 64] = x2*cs + x1*sn;
}

// ---------------- SGEMM: C = A(MxK) @ B(KxN) [+ Res], 128x128x8 tile ----------------
__global__ __launch_bounds__(256) void sgemm_kernel(
    const float* __restrict__ A, const float* __restrict__ B,
    const float* __restrict__ Res, float* __restrict__ C,
    int M, int N, int K)
{
    __shared__ float As[8][128];
    __shared__ float Bs[8][128];
    int tid = threadIdx.x;
    int bm = blockIdx.y * 128;
    int bn = blockIdx.x * 128;
    int arow = tid >> 1, acol = (tid & 1) * 4;      // A tile: 128 rows x 8 k
    int brow = tid >> 5, bcol = (tid & 31) * 4;     // B tile: 8 k x 128 cols
    int tx = tid & 15, ty = tid >> 4;               // 16x16 threads, 8x8 each

    const float* Aptr = A + (size_t)(bm + arow) * K + acol;
    const float* Bptr = B + (size_t)brow * N + bn + bcol;

    float acc[8][8];
    #pragma unroll
    for (int i = 0; i < 8; i++)
        #pragma unroll
        for (int j = 0; j < 8; j++) acc[i][j] = 0.f;

    for (int k0 = 0; k0 < K; k0 += 8) {
        float4 av = *(const float4*)Aptr;
        float4 bv = *(const float4*)Bptr;
        As[acol + 0][arow] = av.x;
        As[acol + 1][arow] = av.y;
        As[acol + 2][arow] = av.z;
        As[acol + 3][arow] = av.w;
        *(float4*)&Bs[brow][bcol] = bv;
        __syncthreads();
        #pragma unroll
        for (int kk = 0; kk < 8; kk++) {
            float ar[8], br[8];
            *(float4*)&ar[0] = *(const float4*)&As[kk][ty * 8];
            *(float4*)&ar[4] = *(const float4*)&As[kk][ty * 8 + 4];
            *(float4*)&br[0] = *(const float4*)&Bs[kk][tx * 8];
            *(float4*)&br[4] = *(const float4*)&Bs[kk][tx * 8 + 4];
            #pragma unroll
            for (int i = 0; i < 8; i++)
                #pragma unroll
                for (int j = 0; j < 8; j++)
                    acc[i][j] += ar[i] * br[j];
        }
        __syncthreads();
        Aptr += 8;
        Bptr += (size_t)8 * N;
    }

    #pragma unroll
    for (int i = 0; i < 8; i++) {
        size_t row = bm + ty * 8 + i;
        #pragma unroll
        for (int j = 0; j < 8; j += 4) {
            size_t col = bn + tx * 8 + j;
            float4 o = make_float4(acc[i][j], acc[i][j+1], acc[i][j+2], acc[i][j+3]);
            if (Res) {
                float4 rv = *(const float4*)&Res[row * N + col];
                o.x += rv.x; o.y += rv.y; o.z += rv.z; o.w += rv.w;
            }
            *(float4*)&C[row * N + col] = o;
        }
    }
}

// ---------------- Flash attention (fp32, causal, GQA rep=4) ----------------
// grid: (L/64, QH, B), block 256. Q tile 64 rows (8 per warp), K tiles of 64.
#define TQ 64
#define TK 64
#define KTS 65                        // padded stride for transposed K (bank-conflict-free)
#define ATTN_SMEM ((TQ*HD + HD*KTS + TK*HD) * 4)   // 98816 bytes

__global__ __launch_bounds__(256) void attn_kernel(
    const float* __restrict__ Q, const float* __restrict__ K,
    const float* __restrict__ V, float* __restrict__ O)
{
    extern __shared__ float sm[];
    float* sQ  = sm;                  // [TQ][HD]
    float* sKt = sQ + TQ * HD;        // [HD][KTS]  (transposed)
    float* sV  = sKt + HD * KTS;      // [TK][HD]

    int qt = blockIdx.x, h = blockIdx.y, b = blockIdx.z;
    int kh = h >> 2;                  // rep = QH/KVH = 4
    int tid = threadIdx.x;
    int warp = tid >> 5, lane = tid & 31;
    int q0 = qt * TQ;

    // load Q tile (float4, coalesced)
    #pragma unroll
    for (int it = 0; it < (TQ * HD / 4) / 256; it++) {
        int idx = it * 256 + tid;
        int r = idx >> 5, c4 = idx & 31;
        float4 v = *(const float4*)(Q + ((size_t)((b*LL + q0 + r)*NQH + h))*HD + c4*4);
        *(float4*)(sQ + r * HD + c4 * 4) = v;
    }

    float o[8][4], m[8], l[8];
    #pragma unroll
    for (int r = 0; r < 8; r++) {
        m[r] = -1e30f; l[r] = 0.f;
        o[r][0] = o[r][1] = o[r][2] = o[r][3] = 0.f;
    }
    const float scale = 0.08838834764831845f;  // 1/sqrt(128)

    for (int kt = 0; kt <= qt; kt++) {
        int kb = kt * TK;
        __syncthreads();
        // K tile transposed, scalar loads (coalesced global), stride-65 smem (conflict-free)
        #pragma unroll
        for (int it = 0; it < (TK * HD) / 256; it++) {
            int idx = it * 256 + tid;
            int j = idx >> 7, d = idx & 127;
            sKt[d * KTS + j] = K[((size_t)((b*LL + kb + j)*NKVH + kh))*HD + d];
        }
        // V tile direct (float4)
        #pragma unroll
        for (int it = 0; it < (TK * HD / 4) / 256; it++) {
            int idx = it * 256 + tid;
            int j = idx >> 5, c4 = idx & 31;
            float4 v = *(const float4*)(V + ((size_t)((b*LL + kb + j)*NKVH + kh))*HD + c4*4);
            *(float4*)(sV + j * HD + c4 * 4) = v;
        }
        __syncthreads();

        #pragma unroll
        for (int rr = 0; rr < 8; rr++) {
            int r = warp * 8 + rr;
            int qi = q0 + r;
            if (kb > qi) continue;                 // uniform across warp
            // scores: lane owns keys (lane) and (lane+32)
            float s1 = 0.f, s2 = 0.f;
            const float* qrow = sQ + r * HD;
            #pragma unroll
            for (int d0 = 0; d0 < HD; d0 += 4) {
                float4 qv = *(const float4*)(qrow + d0);
                s1 += qv.x * sKt[(d0+0)*KTS + lane];
                s1 += qv.y * sKt[(d0+1)*KTS + lane];
                s1 += qv.z * sKt[(d0+2)*KTS + lane];
                s1 += qv.w * sKt[(d0+3)*KTS + lane];
                s2 += qv.x * sKt[(d0+0)*KTS + lane + 32];
                s2 += qv.y * sKt[(d0+1)*KTS + lane + 32];
                s2 += qv.z * sKt[(d0+2)*KTS + lane + 32];
                s2 += qv.w * sKt[(d0+3)*KTS + lane + 32];
            }
            s1 = (kb + lane      <= qi) ? s1 * scale : -1e30f;
            s2 = (kb + lane + 32 <= qi) ? s2 * scale : -1e30f;
            float mx = fmaxf(s1, s2);
            #pragma unroll
            for (int off = 16; off; off >>= 1)
                mx = fmaxf(mx, __shfl_xor_sync(0xffffffffu, mx, off));
            float mnew = fmaxf(m[rr], mx);
            float p1 = __expf(s1 - mnew);
            float p2 = __expf(s2 - mnew);
            float ps = p1 + p2;
            #pragma unroll
            for (int off = 16; off; off >>= 1)
                ps += __shfl_xor_sync(0xffffffffu, ps, off);
            float alpha = __expf(m[rr] - mnew);
            m[rr] = mnew;
            l[rr] = l[rr] * alpha + ps;
            o[rr][0] *= alpha; o[rr][1] *= alpha; o[rr][2] *= alpha; o[rr][3] *= alpha;
            // O += P @ V ; p broadcast via shfl, V float4 per lane (d = lane*4..)
            const float* vb = sV + lane * 4;
            #pragma unroll 8
            for (int j = 0; j < 32; j++) {
                float pj = __shfl_sync(0xffffffffu, p1, j);
                float4 v = *(const float4*)(vb + j * HD);
                o[rr][0] += pj * v.x; o[rr][1] += pj * v.y;
                o[rr][2] += pj * v.z; o[rr][3] += pj * v.w;
            }
            #pragma unroll 8
            for (int j = 0; j < 32; j++) {
                float pj = __shfl_sync(0xffffffffu, p2, j);
                float4 v = *(const float4*)(vb + (j + 32) * HD);
                o[rr][0] += pj * v.x; o[rr][1] += pj * v.y;
                o[rr][2] += pj * v.z; o[rr][3] += pj * v.w;
            }
        }
    }

    #pragma unroll
    for (int rr = 0; rr < 8; rr++) {
        int r = warp * 8 + rr;
        int qi = q0 + r;
        float inv = 1.0f / l[rr];
        float4 v = make_float4(o[rr][0]*inv, o[rr][1]*inv, o[rr][2]*inv, o[rr][3]*inv);
        *(float4*)(O + ((size_t)((b*LL + qi)*NQH + h))*HD + lane*4) = v;
    }
}

// ---------------- silu(g) * u (float4) ----------------
__global__ void silu_mul_kernel(const float* __restrict__ g, const float* __restrict__ u,
                                float* __restrict__ out, int n4)
{
    int i = blockIdx.x * blockDim.x + threadIdx.x;
    if (i >= n4) return;
    float4 gv = ((const float4*)g)[i];
    float4 uv = ((const float4*)u)[i];
    float4 o;
    o.x = gv.x / (1.f + __expf(-gv.x)) * uv.x;
    o.y = gv.y / (1.f + __expf(-gv.y)) * uv.y;
    o.z = gv.z / (1.f + __expf(-gv.z)) * uv.z;
    o.w = gv.w / (1.f + __expf(-gv.w)) * uv.w;
    ((float4*)out)[i] = o;
}

// ---------------- launch ----------------
extern "C" void kernel_launch(void* const* d_in, const int* in_sizes, int n_in,
                              void* d_out, int out_size)
{
    const float* x   = (const float*)d_in[0];
    const float* ln1 = (const float*)d_in[1];
    const float* wq  = (const float*)d_in[2];
    const float* wk  = (const float*)d_in[3];
    const float* wv  = (const float*)d_in[4];
    const float* wo  = (const float*)d_in[5];
    const float* ln2 = (const float*)d_in[6];
    const float* wg  = (const float*)d_in[7];
    const float* wu  = (const float*)d_in[8];
    const float* wd  = (const float*)d_in[9];
    float* out = (float*)d_out;

    float *h, *q, *k, *v, *ctx, *x1, *h2, *g, *u;
    cudaGetSymbolAddress((void**)&h,   g_h);
    cudaGetSymbolAddress((void**)&q,   g_q);
    cudaGetSymbolAddress((void**)&k,   g_k);
    cudaGetSymbolAddress((void**)&v,   g_v);
    cudaGetSymbolAddress((void**)&ctx, g_ctx);
    cudaGetSymbolAddress((void**)&x1,  g_x1);
    cudaGetSymbolAddress((void**)&h2,  g_h2);
    cudaGetSymbolAddress((void**)&g,   g_g);
    cudaGetSymbolAddress((void**)&u,   g_u);

    cudaFuncSetAttribute(attn_kernel, cudaFuncAttributeMaxDynamicSharedMemorySize, ATTN_SMEM);

    // 1) rmsnorm1
    rmsnorm_kernel<<<ROWS, 256>>>(x, ln1, h);
    // 2) qkv projections
    sgemm_kernel<<<dim3((NQH*HD)/128,  ROWS/128), 256>>>(h, wq, nullptr, q, ROWS, NQH*HD,  DD);
    sgemm_kernel<<<dim3((NKVH*HD)/128, ROWS/128), 256>>>(h, wk, nullptr, k, ROWS, NKVH*HD, DD);
    sgemm_kernel<<<dim3((NKVH*HD)/128, ROWS/128), 256>>>(h, wv, nullptr, v, ROWS, NKVH*HD, DD);
    // 3) rope (in place)
    {
        int tq = ROWS * NQH * 64;
        rope_kernel<<<(tq + 255) / 256, 256>>>(q, NQH, tq);
        int tk = ROWS * NKVH * 64;
        rope_kernel<<<(tk + 255) / 256, 256>>>(k, NKVH, tk);
    }
    // 4) attention
    attn_kernel<<<dim3(LL / TQ, NQH, BB), 256, ATTN_SMEM>>>(q, k, v, ctx);
    // 5) output proj + residual
    sgemm_kernel<<<dim3(DD/128, ROWS/128), 256>>>(ctx, wo, x, x1, ROWS, DD, DD);
    // 6) rmsnorm2
    rmsnorm_kernel<<<ROWS, 256>>>(x1, ln2, h2);
    // 7) ffn up/gate
    sgemm_kernel<<<dim3(FFND/128, ROWS/128), 256>>>(h2, wg, nullptr, g, ROWS, FFND, DD);
    sgemm_kernel<<<dim3(FFND/128, ROWS/128), 256>>>(h2, wu, nullptr, u, ROWS, FFND, DD);
    // 8) silu*mul (into g)
    {
        int n4 = ROWS * FFND / 4;
        silu_mul_kernel<<<(n4 + 255) / 256, 256>>>(g, u, g, n4);
    }
    // 9) down proj + residual -> out
    sgemm_kernel<<<dim3(DD/128, ROWS/128), 256>>>(g, wd, x1, out, ROWS, DD, FFND);
}

// round 3
// speedup vs baseline: 1.2984x; 1.2984x over previous
#include <cuda_runtime.h>
#include <cuda_bf16.h>
#include <mma.h>
#include <math.h>
#include <cstdint>

using namespace nvcuda;

// Problem constants
#define BB 2
#define LL 2048
#define DD 1024
#define NQH 8
#define NKVH 2
#define HD 128
#define FFND 4096
#define ROWS (BB*LL)            // 4096
#define EPSV 1.1920929e-07f

// ---------------- scratch (device globals; no allocs allowed) ----------------
__device__ float g_h  [ROWS*DD];        // rmsnorm1 out
__device__ float g_q  [ROWS*NQH*HD];    // q proj
__device__ float g_k  [ROWS*NKVH*HD];   // k proj
__device__ float g_v  [ROWS*NKVH*HD];   // v proj
__device__ float g_ctx[ROWS*NQH*HD];    // attention out
__device__ float g_x1 [ROWS*DD];        // post-attn residual stream
__device__ float g_h2 [ROWS*DD];        // rmsnorm2 out
__device__ float g_g  [ROWS*FFND];      // gate proj (reused for silu*u)
__device__ float g_u  [ROWS*FFND];      // up proj

// ---------------- RMSNorm ----------------
__global__ __launch_bounds__(256) void rmsnorm_kernel(
    const float* __restrict__ x, const float* __restrict__ w, float* __restrict__ out)
{
    int row = blockIdx.x;
    const float4* xr = (const float4*)(x + (size_t)row * DD);
    float4 v = xr[threadIdx.x];
    float s = v.x*v.x + v.y*v.y + v.z*v.z + v.w*v.w;
    #pragma unroll
    for (int off = 16; off; off >>= 1) s += __shfl_xor_sync(0xffffffffu, s, off);
    __shared__ float red[8];
    if ((threadIdx.x & 31) == 0) red[threadIdx.x >> 5] = s;
    __syncthreads();
    float tot = red[0]+red[1]+red[2]+red[3]+red[4]+red[5]+red[6]+red[7];
    float r = rsqrtf(tot * (1.0f/DD) + EPSV);
    const float4 wv = ((const float4*)w)[threadIdx.x];
    float4 o = make_float4(v.x*r*wv.x, v.y*r*wv.y, v.z*r*wv.z, v.w*r*wv.w);
    ((float4*)(out + (size_t)row * DD))[threadIdx.x] = o;
}

// ---------------- RoPE (in-place) ----------------
__global__ void rope_kernel(float* __restrict__ x, int H, int total)
{
    int idx = blockIdx.x * blockDim.x + threadIdx.x;
    if (idx >= total) return;
    int d = idx & 63;
    int t = idx >> 6;
    int pos = (t / H) & (LL - 1);
    float freq = powf(10000.0f, (float)d * (2.0f / HD));
    float rad = (float)pos / freq;
    float sn, cs;
    sincosf(rad, &sn, &cs);
    float* p = x + (size_t)t * HD;
    float x1 = p[d], x2 = p[d + 64];
    p[d]      = x1*cs - x2*sn;
    p[d + 64] = x2*cs + x1*sn;
}

// ---------------- tf32 tensor-core GEMM core ----------------
// Block tile 128x128x32, 2-stage cp.async pipeline, 8 warps (32x64 warp tile)
#define GASZ (128*36)
#define GBSZ (32*132)
#define GEMM_SMEM ((2*GASZ + 2*GBSZ)*4)   // 70656 bytes

__device__ __forceinline__ void cp_async16(float* smem, const float* g)
{
    unsigned int s = (unsigned int)__cvta_generic_to_shared(smem);
    asm volatile("cp.async.cg.shared.global [%0], [%1], 16;\n" :: "r"(s), "l"(g));
}

__device__ __forceinline__ void gemm_core(
    const float* __restrict__ A, const float* __restrict__ B,
    const float* __restrict__ Res, float* __restrict__ C,
    int K, int ldb, int ldc, int bm0, int col0)
{
    extern __shared__ float smem[];
    float* As = smem;              // [2][128][36]
    float* Bs = smem + 2*GASZ;     // [2][32][132]

    int tid  = threadIdx.x;
    int warp = tid >> 5;
    int wm = warp & 3;             // 0..3 -> 32-row slab
    int wn = warp >> 2;            // 0..1 -> 64-col slab

    wmma::fragment<wmma::accumulator, 16,16,8, float> acc[2][4];
    #pragma unroll
    for (int i = 0; i < 2; i++)
        #pragma unroll
        for (int j = 0; j < 4; j++)
            wmma::fill_fragment(acc[i][j], 0.0f);

    int arow = tid >> 3, acol = (tid & 7) << 2;    // A: 32 rows x 32 cols per pass
    int brow = tid >> 5, bcol = (tid & 31) << 2;   // B: 8 rows x 128 cols per pass

    int nk = K >> 5;

    // prologue: stage 0
    {
        #pragma unroll
        for (int p = 0; p < 4; p++) {
            int r = arow + p * 32;
            cp_async16(As + r*36 + acol, A + (size_t)(bm0 + r)*K + acol);
        }
        #pragma unroll
        for (int p = 0; p < 4; p++) {
            int kk = brow + p * 8;
            cp_async16(Bs + kk*132 + bcol, B + (size_t)kk*ldb + col0 + bcol);
        }
        asm volatile("cp.async.commit_group;\n" ::);
    }

    for (int kt = 0; kt < nk; kt++) {
        asm volatile("cp.async.wait_group 0;\n" ::);
        __syncthreads();

        if (kt + 1 < nk) {
            int s = (kt + 1) & 1;
            int k0 = (kt + 1) << 5;
            #pragma unroll
            for (int p = 0; p < 4; p++) {
                int r = arow + p * 32;
                cp_async16(As + s*GASZ + r*36 + acol, A + (size_t)(bm0 + r)*K + k0 + acol);
            }
            #pragma unroll
            for (int p = 0; p < 4; p++) {
                int kk = brow + p * 8;
                cp_async16(Bs + s*GBSZ + kk*132 + bcol, B + (size_t)(k0 + kk)*ldb + col0 + bcol);
            }
            asm volatile("cp.async.commit_group;\n" ::);
        }

        int s = kt & 1;
        #pragma unroll
        for (int ks = 0; ks < 4; ks++) {
            wmma::fragment<wmma::matrix_a, 16,16,8, wmma::precision::tf32, wmma::row_major> af[2];
            wmma::fragment<wmma::matrix_b, 16,16,8, wmma::precision::tf32, wmma::row_major> bf[4];
            #pragma unroll
            for (int i = 0; i < 2; i++) {
                wmma::load_matrix_sync(af[i], As + s*GASZ + (wm*32 + i*16)*36 + ks*8, 36);
                #pragma unroll
                for (int e = 0; e < af[i].num_elements; e++)
                    af[i].x[e] = wmma::__float_to_tf32(af[i].x[e]);
            }
            #pragma unroll
            for (int j = 0; j < 4; j++) {
                wmma::load_matrix_sync(bf[j], Bs + s*GBSZ + (ks*8)*132 + wn*64 + j*16, 132);
                #pragma unroll
                for (int e = 0; e < bf[j].num_elements; e++)
                    bf[j].x[e] = wmma::__float_to_tf32(bf[j].x[e]);
            }
            #pragma unroll
            for (int i = 0; i < 2; i++)
                #pragma unroll
                for (int j = 0; j < 4; j++)
                    wmma::mma_sync(acc[i][j], af[i], bf[j], acc[i][j]);
        }
    }

    // epilogue (+ optional residual)
    #pragma unroll
    for (int i = 0; i < 2; i++) {
        int r0 = bm0 + wm*32 + i*16;
        #pragma unroll
        for (int j = 0; j < 4; j++) {
            int c0 = col0 + wn*64 + j*16;
            if (Res) {
                wmma::fragment<wmma::accumulator, 16,16,8, float> rf;
                wmma::load_matrix_sync(rf, Res + (size_t)r0*ldc + c0, ldc, wmma::mem_row_major);
                #pragma unroll
                for (int e = 0; e < rf.num_elements; e++)
                    acc[i][j].x[e] += rf.x[e];
            }
            wmma::store_matrix_sync(C + (size_t)r0*ldc + c0, acc[i][j], ldc, wmma::mem_row_major);
        }
    }
}

// generic GEMM: C = A @ B [+ Res], N = ldb = ldc
__global__ __launch_bounds__(256) void gemm_kernel(
    const float* __restrict__ A, const float* __restrict__ B,
    const float* __restrict__ Res, float* __restrict__ C, int K, int N)
{
    gemm_core(A, B, Res, C, K, N, N, blockIdx.y * 128, blockIdx.x * 128);
}

// fused QKV: one launch covering wq (8 col-blocks), wk (2), wv (2)
__global__ __launch_bounds__(256) void qkv_kernel(
    const float* __restrict__ h,
    const float* __restrict__ wq, const float* __restrict__ wk, const float* __restrict__ wv,
    float* __restrict__ q, float* __restrict__ k, float* __restrict__ v)
{
    int bn = blockIdx.x;
    const float* B; float* C; int ldn; int c0;
    if (bn < 8)       { B = wq; C = q; ldn = NQH*HD;  c0 = bn * 128; }
    else if (bn < 10) { B = wk; C = k; ldn = NKVH*HD; c0 = (bn - 8) * 128; }
    else              { B = wv; C = v; ldn = NKVH*HD; c0 = (bn - 10) * 128; }
    gemm_core(h, B, nullptr, C, DD, ldn, ldn, blockIdx.y * 128, c0);
}

// fused gate+up: bn<32 -> wg, else wu
__global__ __launch_bounds__(256) void gu_kernel(
    const float* __restrict__ h2,
    const float* __restrict__ wg, const float* __restrict__ wu,
    float* __restrict__ g, float* __restrict__ u)
{
    int bn = blockIdx.x;
    const float* B = (bn < 32) ? wg : wu;
    float* C       = (bn < 32) ? g  : u;
    int c0 = (bn & 31) * 128;
    gemm_core(h2, B, nullptr, C, DD, FFND, FFND, blockIdx.y * 128, c0);
}

// ---------------- Flash attention (fp32, causal, GQA rep=4) ----------------
#define TQ 64
#define TK 64
#define KTS 65
#define ATTN_SMEM ((TQ*HD + HD*KTS + TK*HD) * 4)   // 98816 bytes

__global__ __launch_bounds__(256) void attn_kernel(
    const float* __restrict__ Q, const float* __restrict__ K,
    const float* __restrict__ V, float* __restrict__ O)
{
    extern __shared__ float sm[];
    float* sQ  = sm;
    float* sKt = sQ + TQ * HD;
    float* sV  = sKt + HD * KTS;

    int qt = blockIdx.x, h = blockIdx.y, b = blockIdx.z;
    int kh = h >> 2;
    int tid = threadIdx.x;
    int warp = tid >> 5, lane = tid & 31;
    int q0 = qt * TQ;

    #pragma unroll
    for (int it = 0; it < (TQ * HD / 4) / 256; it++) {
        int idx = it * 256 + tid;
        int r = idx >> 5, c4 = idx & 31;
        float4 v = *(const float4*)(Q + ((size_t)((b*LL + q0 + r)*NQH + h))*HD + c4*4);
        *(float4*)(sQ + r * HD + c4 * 4) = v;
    }

    float o[8][4], m[8], l[8];
    #pragma unroll
    for (int r = 0; r < 8; r++) {
        m[r] = -1e30f; l[r] = 0.f;
        o[r][0] = o[r][1] = o[r][2] = o[r][3] = 0.f;
    }
    const float scale = 0.08838834764831845f;

    for (int kt = 0; kt <= qt; kt++) {
        int kb = kt * TK;
        __syncthreads();
        #pragma unroll
        for (int it = 0; it < (TK * HD) / 256; it++) {
            int idx = it * 256 + tid;
            int j = idx >> 7, d = idx & 127;
            sKt[d * KTS + j] = K[((size_t)((b*LL + kb + j)*NKVH + kh))*HD + d];
        }
        #pragma unroll
        for (int it = 0; it < (TK * HD / 4) / 256; it++) {
            int idx = it * 256 + tid;
            int j = idx >> 5, c4 = idx & 31;
            float4 v = *(const float4*)(V + ((size_t)((b*LL + kb + j)*NKVH + kh))*HD + c4*4);
            *(float4*)(sV + j * HD + c4 * 4) = v;
        }
        __syncthreads();

        #pragma unroll
        for (int rr = 0; rr < 8; rr++) {
            int r = warp * 8 + rr;
            int qi = q0 + r;
            if (kb > qi) continue;
            float s1 = 0.f, s2 = 0.f;
            const float* qrow = sQ + r * HD;
            #pragma unroll
            for (int d0 = 0; d0 < HD; d0 += 4) {
                float4 qv = *(const float4*)(qrow + d0);
                s1 += qv.x * sKt[(d0+0)*KTS + lane];
                s1 += qv.y * sKt[(d0+1)*KTS + lane];
                s1 += qv.z * sKt[(d0+2)*KTS + lane];
                s1 += qv.w * sKt[(d0+3)*KTS + lane];
                s2 += qv.x * sKt[(d0+0)*KTS + lane + 32];
                s2 += qv.y * sKt[(d0+1)*KTS + lane + 32];
                s2 += qv.z * sKt[(d0+2)*KTS + lane + 32];
                s2 += qv.w * sKt[(d0+3)*KTS + lane + 32];
            }
            s1 = (kb + lane      <= qi) ? s1 * scale : -1e30f;
            s2 = (kb + lane + 32 <= qi) ? s2 * scale : -1e30f;
            float mx = fmaxf(s1, s2);
            #pragma unroll
            for (int off = 16; off; off >>= 1)
                mx = fmaxf(mx, __shfl_xor_sync(0xffffffffu, mx, off));
            float mnew = fmaxf(m[rr], mx);
            float p1 = __expf(s1 - mnew);
            float p2 = __expf(s2 - mnew);
            float ps = p1 + p2;
            #pragma unroll
            for (int off = 16; off; off >>= 1)
                ps += __shfl_xor_sync(0xffffffffu, ps, off);
            float alpha = __expf(m[rr] - mnew);
            m[rr] = mnew;
            l[rr] = l[rr] * alpha + ps;
            o[rr][0] *= alpha; o[rr][1] *= alpha; o[rr][2] *= alpha; o[rr][3] *= alpha;
            const float* vb = sV + lane * 4;
            #pragma unroll 8
            for (int j = 0; j < 32; j++) {
                float pj = __shfl_sync(0xffffffffu, p1, j);
                float4 v = *(const float4*)(vb + j * HD);
                o[rr][0] += pj * v.x; o[rr][1] += pj * v.y;
                o[rr][2] += pj * v.z; o[rr][3] += pj * v.w;
            }
            #pragma unroll 8
            for (int j = 0; j < 32; j++) {
                float pj = __shfl_sync(0xffffffffu, p2, j);
                float4 v = *(const float4*)(vb + (j + 32) * HD);
                o[rr][0] += pj * v.x; o[rr][1] += pj * v.y;
                o[rr][2] += pj * v.z; o[rr][3] += pj * v.w;
            }
        }
    }

    #pragma unroll
    for (int rr = 0; rr < 8; rr++) {
        int r = warp * 8 + rr;
        int qi = q0 + r;
        float inv = 1.0f / l[rr];
        float4 v = make_float4(o[rr][0]*inv, o[rr][1]*inv, o[rr][2]*inv, o[rr][3]*inv);
        *(float4*)(O + ((size_t)((b*LL + qi)*NQH + h))*HD + lane*4) = v;
    }
}

// ---------------- silu(g) * u ----------------
__global__ void silu_mul_kernel(const float* __restrict__ g, const float* __restrict__ u,
                                float* __restrict__ out, int n4)
{
    int i = blockIdx.x * blockDim.x + threadIdx.x;
    if (i >= n4) return;
    float4 gv = ((const float4*)g)[i];
    float4 uv = ((const float4*)u)[i];
    float4 o;
    o.x = gv.x / (1.f + __expf(-gv.x)) * uv.x;
    o.y = gv.y / (1.f + __expf(-gv.y)) * uv.y;
    o.z = gv.z / (1.f + __expf(-gv.z)) * uv.z;
    o.w = gv.w / (1.f + __expf(-gv.w)) * uv.w;
    ((float4*)out)[i] = o;
}

// ---------------- launch ----------------
extern "C" void kernel_launch(void* const* d_in, const int* in_sizes, int n_in,
                              void* d_out, int out_size)
{
    const float* x   = (const float*)d_in[0];
    const float* ln1 = (const float*)d_in[1];
    const float* wq  = (const float*)d_in[2];
    const float* wk  = (const float*)d_in[3];
    const float* wv  = (const float*)d_in[4];
    const float* wo  = (const float*)d_in[5];
    const float* ln2 = (const float*)d_in[6];
    const float* wg  = (const float*)d_in[7];
    const float* wu  = (const float*)d_in[8];
    const float* wd  = (const float*)d_in[9];
    float* out = (float*)d_out;

    float *h, *q, *k, *v, *ctx, *x1, *h2, *g, *u;
    cudaGetSymbolAddress((void**)&h,   g_h);
    cudaGetSymbolAddress((void**)&q,   g_q);
    cudaGetSymbolAddress((void**)&k,   g_k);
    cudaGetSymbolAddress((void**)&v,   g_v);
    cudaGetSymbolAddress((void**)&ctx, g_ctx);
    cudaGetSymbolAddress((void**)&x1,  g_x1);
    cudaGetSymbolAddress((void**)&h2,  g_h2);
    cudaGetSymbolAddress((void**)&g,   g_g);
    cudaGetSymbolAddress((void**)&u,   g_u);

    cudaFuncSetAttribute(attn_kernel, cudaFuncAttributeMaxDynamicSharedMemorySize, ATTN_SMEM);
    cudaFuncSetAttribute(gemm_kernel, cudaFuncAttributeMaxDynamicSharedMemorySize, GEMM_SMEM);
    cudaFuncSetAttribute(qkv_kernel,  cudaFuncAttributeMaxDynamicSharedMemorySize, GEMM_SMEM);
    cudaFuncSetAttribute(gu_kernel,   cudaFuncAttributeMaxDynamicSharedMemorySize, GEMM_SMEM);

    // 1) rmsnorm1
    rmsnorm_kernel<<<ROWS, 256>>>(x, ln1, h);
    // 2) fused qkv projections (tensor cores)
    qkv_kernel<<<dim3(12, ROWS/128), 256, GEMM_SMEM>>>(h, wq, wk, wv, q, k, v);
    // 3) rope (in place)
    {
        int tq = ROWS * NQH * 64;
        rope_kernel<<<(tq + 255) / 256, 256>>>(q, NQH, tq);
        int tk = ROWS * NKVH * 64;
        rope_kernel<<<(tk + 255) / 256, 256>>>(k, NKVH, tk);
    }
    // 4) attention
    attn_kernel<<<dim3(LL / TQ, NQH, BB), 256, ATTN_SMEM>>>(q, k, v, ctx);
    // 5) output proj + residual
    gemm_kernel<<<dim3(DD/128, ROWS/128), 256, GEMM_SMEM>>>(ctx, wo, x, x1, DD, DD);
    // 6) rmsnorm2
    rmsnorm_kernel<<<ROWS, 256>>>(x1, ln2, h2);
    // 7) fused ffn gate+up
    gu_kernel<<<dim3(64, ROWS/128), 256, GEMM_SMEM>>>(h2, wg, wu, g, u);
    // 8) silu*mul
    {
        int n4 = ROWS * FFND / 4;
        silu_mul_kernel<<<(n4 + 255) / 256, 256>>>(g, u, g, n4);
    }
    // 9) down proj + residual -> out
    gemm_kernel<<<dim3(DD/128, ROWS/128), 256, GEMM_SMEM>>>(g, wd, x1, out, FFND, DD);
}

// round 5
// speedup vs baseline: 1.8085x; 1.3928x over previous
#include <cuda_runtime.h>
#include <cuda_bf16.h>
#include <mma.h>
#include <math.h>
#include <cstdint>

using namespace nvcuda;

// Problem constants
#define BB 2
#define LL 2048
#define DD 1024
#define NQH 8
#define NKVH 2
#define HD 128
#define FFND 4096
#define ROWS (BB*LL)            // 4096
#define EPSV 1.1920929e-07f

// ---------------- scratch (device globals; no allocs allowed) ----------------
__device__ float g_h  [ROWS*DD];        // rmsnorm1 out
__device__ float g_q  [ROWS*NQH*HD];    // q proj
__device__ float g_k  [ROWS*NKVH*HD];   // k proj
__device__ float g_v  [ROWS*NKVH*HD];   // v proj
__device__ float g_ctx[ROWS*NQH*HD];    // attention out
__device__ float g_x1 [ROWS*DD];        // post-attn residual stream
__device__ float g_h2 [ROWS*DD];        // rmsnorm2 out
__device__ float g_g  [ROWS*FFND];      // gate proj (reused for silu*u)
__device__ float g_u  [ROWS*FFND];      // up proj

// ---------------- RMSNorm ----------------
__global__ __launch_bounds__(256) void rmsnorm_kernel(
    const float* __restrict__ x, const float* __restrict__ w, float* __restrict__ out)
{
    int row = blockIdx.x;
    const float4* xr = (const float4*)(x + (size_t)row * DD);
    float4 v = xr[threadIdx.x];
    float s = v.x*v.x + v.y*v.y + v.z*v.z + v.w*v.w;
    #pragma unroll
    for (int off = 16; off; off >>= 1) s += __shfl_xor_sync(0xffffffffu, s, off);
    __shared__ float red[8];
    if ((threadIdx.x & 31) == 0) red[threadIdx.x >> 5] = s;
    __syncthreads();
    float tot = red[0]+red[1]+red[2]+red[3]+red[4]+red[5]+red[6]+red[7];
    float r = rsqrtf(tot * (1.0f/DD) + EPSV);
    const float4 wv = ((const float4*)w)[threadIdx.x];
    float4 o = make_float4(v.x*r*wv.x, v.y*r*wv.y, v.z*r*wv.z, v.w*r*wv.w);
    ((float4*)(out + (size_t)row * DD))[threadIdx.x] = o;
}

// ---------------- RoPE (in-place) ----------------
__global__ void rope_kernel(float* __restrict__ x, int H, int total)
{
    int idx = blockIdx.x * blockDim.x + threadIdx.x;
    if (idx >= total) return;
    int d = idx & 63;
    int t = idx >> 6;
    int pos = (t / H) & (LL - 1);
    float freq = powf(10000.0f, (float)d * (2.0f / HD));
    float rad = (float)pos / freq;
    float sn, cs;
    sincosf(rad, &sn, &cs);
    float* p = x + (size_t)t * HD;
    float x1 = p[d], x2 = p[d + 64];
    p[d]      = x1*cs - x2*sn;
    p[d + 64] = x2*cs + x1*sn;
}

// ---------------- tf32 tensor-core GEMM core ----------------
// Block tile 128x128x32, 2-stage cp.async pipeline, 8 warps (32x64 warp tile)
#define GASZ (128*36)
#define GBSZ (32*132)
#define GEMM_SMEM ((2*GASZ + 2*GBSZ)*4)   // 70656 bytes

__device__ __forceinline__ void cp_async16(float* smem, const float* g)
{
    unsigned int s = (unsigned int)__cvta_generic_to_shared(smem);
    asm volatile("cp.async.cg.shared.global [%0], [%1], 16;\n" :: "r"(s), "l"(g));
}

__device__ __forceinline__ void gemm_core(
    const float* __restrict__ A, const float* __restrict__ B,
    const float* __restrict__ Res, float* __restrict__ C,
    int K, int ldb, int ldc, int bm0, int col0)
{
    extern __shared__ float smem[];
    float* As = smem;              // [2][128][36]
    float* Bs = smem + 2*GASZ;     // [2][32][132]

    int tid  = threadIdx.x;
    int warp = tid >> 5;
    int wm = warp & 3;             // 0..3 -> 32-row slab
    int wn = warp >> 2;            // 0..1 -> 64-col slab

    wmma::fragment<wmma::accumulator, 16,16,8, float> acc[2][4];
    #pragma unroll
    for (int i = 0; i < 2; i++)
        #pragma unroll
        for (int j = 0; j < 4; j++)
            wmma::fill_fragment(acc[i][j], 0.0f);

    int arow = tid >> 3, acol = (tid & 7) << 2;    // A: 32 rows x 32 cols per pass
    int brow = tid >> 5, bcol = (tid & 31) << 2;   // B: 8 rows x 128 cols per pass

    int nk = K >> 5;

    // prologue: stage 0
    {
        #pragma unroll
        for (int p = 0; p < 4; p++) {
            int r = arow + p * 32;
            cp_async16(As + r*36 + acol, A + (size_t)(bm0 + r)*K + acol);
        }
        #pragma unroll
        for (int p = 0; p < 4; p++) {
            int kk = brow + p * 8;
            cp_async16(Bs + kk*132 + bcol, B + (size_t)kk*ldb + col0 + bcol);
        }
        asm volatile("cp.async.commit_group;\n" ::);
    }

    for (int kt = 0; kt < nk; kt++) {
        asm volatile("cp.async.wait_group 0;\n" ::);
        __syncthreads();

        if (kt + 1 < nk) {
            int s = (kt + 1) & 1;
            int k0 = (kt + 1) << 5;
            #pragma unroll
            for (int p = 0; p < 4; p++) {
                int r = arow + p * 32;
                cp_async16(As + s*GASZ + r*36 + acol, A + (size_t)(bm0 + r)*K + k0 + acol);
            }
            #pragma unroll
            for (int p = 0; p < 4; p++) {
                int kk = brow + p * 8;
                cp_async16(Bs + s*GBSZ + kk*132 + bcol, B + (size_t)(k0 + kk)*ldb + col0 + bcol);
            }
            asm volatile("cp.async.commit_group;\n" ::);
        }

        int s = kt & 1;
        #pragma unroll
        for (int ks = 0; ks < 4; ks++) {
            wmma::fragment<wmma::matrix_a, 16,16,8, wmma::precision::tf32, wmma::row_major> af[2];
            wmma::fragment<wmma::matrix_b, 16,16,8, wmma::precision::tf32, wmma::row_major> bf[4];
            #pragma unroll
            for (int i = 0; i < 2; i++) {
                wmma::load_matrix_sync(af[i], As + s*GASZ + (wm*32 + i*16)*36 + ks*8, 36);
                #pragma unroll
                for (int e = 0; e < af[i].num_elements; e++)
                    af[i].x[e] = wmma::__float_to_tf32(af[i].x[e]);
            }
            #pragma unroll
            for (int j = 0; j < 4; j++) {
                wmma::load_matrix_sync(bf[j], Bs + s*GBSZ + (ks*8)*132 + wn*64 + j*16, 132);
                #pragma unroll
                for (int e = 0; e < bf[j].num_elements; e++)
                    bf[j].x[e] = wmma::__float_to_tf32(bf[j].x[e]);
            }
            #pragma unroll
            for (int i = 0; i < 2; i++)
                #pragma unroll
                for (int j = 0; j < 4; j++)
                    wmma::mma_sync(acc[i][j], af[i], bf[j], acc[i][j]);
        }
    }

    // epilogue (+ optional residual)
    #pragma unroll
    for (int i = 0; i < 2; i++) {
        int r0 = bm0 + wm*32 + i*16;
        #pragma unroll
        for (int j = 0; j < 4; j++) {
            int c0 = col0 + wn*64 + j*16;
            if (Res) {
                wmma::fragment<wmma::accumulator, 16,16,8, float> rf;
                wmma::load_matrix_sync(rf, Res + (size_t)r0*ldc + c0, ldc, wmma::mem_row_major);
                #pragma unroll
                for (int e = 0; e < rf.num_elements; e++)
                    acc[i][j].x[e] += rf.x[e];
            }
            wmma::store_matrix_sync(C + (size_t)r0*ldc + c0, acc[i][j], ldc, wmma::mem_row_major);
        }
    }
}

// generic GEMM: C = A @ B [+ Res], N = ldb = ldc
__global__ __launch_bounds__(256) void gemm_kernel(
    const float* __restrict__ A, const float* __restrict__ B,
    const float* __restrict__ Res, float* __restrict__ C, int K, int N)
{
    gemm_core(A, B, Res, C, K, N, N, blockIdx.y * 128, blockIdx.x * 128);
}

// fused QKV: one launch covering wq (8 col-blocks), wk (2), wv (2)
__global__ __launch_bounds__(256) void qkv_kernel(
    const float* __restrict__ h,
    const float* __restrict__ wq, const float* __restrict__ wk, const float* __restrict__ wv,
    float* __restrict__ q, float* __restrict__ k, float* __restrict__ v)
{
    int bn = blockIdx.x;
    const float* B; float* C; int ldn; int c0;
    if (bn < 8)       { B = wq; C = q; ldn = NQH*HD;  c0 = bn * 128; }
    else if (bn < 10) { B = wk; C = k; ldn = NKVH*HD; c0 = (bn - 8) * 128; }
    else              { B = wv; C = v; ldn = NKVH*HD; c0 = (bn - 10) * 128; }
    gemm_core(h, B, nullptr, C, DD, ldn, ldn, blockIdx.y * 128, c0);
}

// fused gate+up: bn<32 -> wg, else wu
__global__ __launch_bounds__(256) void gu_kernel(
    const float* __restrict__ h2,
    const float* __restrict__ wg, const float* __restrict__ wu,
    float* __restrict__ g, float* __restrict__ u)
{
    int bn = blockIdx.x;
    const float* B = (bn < 32) ? wg : wu;
    float* C       = (bn < 32) ? g  : u;
    int c0 = (bn & 31) * 128;
    gemm_core(h2, B, nullptr, C, DD, FFND, FFND, blockIdx.y * 128, c0);
}

// ---------------- Flash attention: wmma tf32 QK^T and PV, scalar fp32 softmax ----------------
#define TQ 64
#define TK 64
#define SP 72                              // S/P tile pitch
#define OP 132                             // PV tile pitch
// sQ(64*128) + sK(64*128) + sV(64*128) + sS(64*72) + sO(64*132)
#define ATTN_SMEM ((3*TQ*HD + TQ*SP + TQ*OP) * 4)   // 150528 bytes

__global__ __launch_bounds__(256) void attn_kernel(
    const float* __restrict__ Q, const float* __restrict__ K,
    const float* __restrict__ V, float* __restrict__ O)
{
    extern __shared__ float sm[];
    float* sQ = sm;                     // [64][128]
    float* sK = sQ + TQ * HD;           // [64][128]
    float* sV = sK + TK * HD;           // [64][128]
    float* sS = sV + TK * HD;           // [64][72]
    float* sO = sS + TQ * SP;           // [64][132]

    int qt = blockIdx.x, h = blockIdx.y, b = blockIdx.z;
    int kh = h >> 2;
    int tid = threadIdx.x;
    int warp = tid >> 5, lane = tid & 31;
    int q0 = qt * TQ;
    int wr = warp & 1, wc = warp >> 1;  // 2x4 warp grid for wmma steps

    // load Q tile
    #pragma unroll
    for (int it = 0; it < (TQ * HD / 4) / 256; it++) {
        int idx = it * 256 + tid;
        int r = idx >> 5, c4 = idx & 31;
        float4 v = *(const float4*)(Q + ((size_t)((b*LL + q0 + r)*NQH + h))*HD + c4*4);
        *(float4*)(sQ + r * HD + c4 * 4) = v;
    }

    float o[8][4], m[8], l[8];
    #pragma unroll
    for (int r = 0; r < 8; r++) {
        m[r] = -1e30f; l[r] = 0.f;
        o[r][0] = o[r][1] = o[r][2] = o[r][3] = 0.f;
    }
    const float scale = 0.08838834764831845f;

    for (int kt = 0; kt <= qt; kt++) {
        int kb = kt * TK;
        __syncthreads();   // A: protect sK/sV/sO reuse
        #pragma unroll
        for (int it = 0; it < (TK * HD / 4) / 256; it++) {
            int idx = it * 256 + tid;
            int j = idx >> 5, c4 = idx & 31;
            float4 kv = *(const float4*)(K + ((size_t)((b*LL + kb + j)*NKVH + kh))*HD + c4*4);
            *(float4*)(sK + j * HD + c4 * 4) = kv;
            float4 vv = *(const float4*)(V + ((size_t)((b*LL + kb + j)*NKVH + kh))*HD + c4*4);
            *(float4*)(sV + j * HD + c4 * 4) = vv;
        }
        __syncthreads();   // B

        // ---- S = Q @ K^T (64x64), warp = 32 rows x 16 cols ----
        {
            wmma::fragment<wmma::accumulator, 16,16,8, float> sacc[2];
            wmma::fill_fragment(sacc[0], 0.0f);
            wmma::fill_fragment(sacc[1], 0.0f);
            #pragma unroll
            for (int kk = 0; kk < 16; kk++) {
                wmma::fragment<wmma::matrix_b, 16,16,8, wmma::precision::tf32, wmma::col_major> bf;
                wmma::load_matrix_sync(bf, sK + wc*16*HD + kk*8, HD);
                #pragma unroll
                for (int e = 0; e < bf.num_elements; e++)
                    bf.x[e] = wmma::__float_to_tf32(bf.x[e]);
                #pragma unroll
                for (int i = 0; i < 2; i++) {
                    wmma::fragment<wmma::matrix_a, 16,16,8, wmma::precision::tf32, wmma::row_major> af;
                    wmma::load_matrix_sync(af, sQ + (wr*32 + i*16)*HD + kk*8, HD);
                    #pragma unroll
                    for (int e = 0; e < af.num_elements; e++)
                        af.x[e] = wmma::__float_to_tf32(af.x[e]);
                    wmma::mma_sync(sacc[i], af, bf, sacc[i]);
                }
            }
            wmma::store_matrix_sync(sS + (wr*32 +  0)*SP + wc*16, sacc[0], SP, wmma::mem_row_major);
            wmma::store_matrix_sync(sS + (wr*32 + 16)*SP + wc*16, sacc[1], SP, wmma::mem_row_major);
        }
        __syncthreads();   // C

        // ---- online softmax: warp owns rows warp*8 .. warp*8+7 ----
        #pragma unroll
        for (int rr = 0; rr < 8; rr++) {
            int row = warp*8 + rr;
            int qi = q0 + row;
            float s1 = sS[row*SP + lane];
            float s2 = sS[row*SP + lane + 32];
            s1 = (kb + lane      <= qi) ? s1 * scale : -1e30f;
            s2 = (kb + lane + 32 <= qi) ? s2 * scale : -1e30f;
            float mx = fmaxf(s1, s2);
            #pragma unroll
            for (int off = 16; off; off >>= 1)
                mx = fmaxf(mx, __shfl_xor_sync(0xffffffffu, mx, off));
            float mnew = fmaxf(m[rr], mx);
            float p1 = __expf(s1 - mnew);
            float p2 = __expf(s2 - mnew);
            float ps = p1 + p2;
            #pragma unroll
            for (int off = 16; off; off >>= 1)
                ps += __shfl_xor_sync(0xffffffffu, ps, off);
            float alpha = __expf(m[rr] - mnew);
            m[rr] = mnew;
            l[rr] = l[rr] * alpha + ps;
            o[rr][0] *= alpha; o[rr][1] *= alpha; o[rr][2] *= alpha; o[rr][3] *= alpha;
            sS[row*SP + lane]      = p1;
            sS[row*SP + lane + 32] = p2;
        }
        __syncthreads();   // D

        // ---- PV = P(64x64) @ V(64x128), warp = 32 rows x 32 cols ----
        {
            wmma::fragment<wmma::accumulator, 16,16,8, float> pacc[2][2];
            #pragma unroll
            for (int i = 0; i < 2; i++)
                #pragma unroll
                for (int j = 0; j < 2; j++)
                    wmma::fill_fragment(pacc[i][j], 0.0f);
            #pragma unroll
            for (int kk = 0; kk < 8; kk++) {
                wmma::fragment<wmma::matrix_a, 16,16,8, wmma::precision::tf32, wmma::row_major> af[2];
                wmma::fragment<wmma::matrix_b, 16,16,8, wmma::precision::tf32, wmma::row_major> bf[2];
                #pragma unroll
                for (int i = 0; i < 2; i++) {
                    wmma::load_matrix_sync(af[i], sS + (wr*32 + i*16)*SP + kk*8, SP);
                    #pragma unroll
                    for (int e = 0; e < af[i].num_elements; e++)
                        af[i].x[e] = wmma::__float_to_tf32(af[i].x[e]);
                }
                #pragma unroll
                for (int j = 0; j < 2; j++) {
                    wmma::load_matrix_sync(bf[j], sV + (kk*8)*HD + wc*32 + j*16, HD);
                    #pragma unroll
                    for (int e = 0; e < bf[j].num_elements; e++)
                        bf[j].x[e] = wmma::__float_to_tf32(bf[j].x[e]);
                }
                #pragma unroll
                for (int i = 0; i < 2; i++)
                    #pragma unroll
                    for (int j = 0; j < 2; j++)
                        wmma::mma_sync(pacc[i][j], af[i], bf[j], pacc[i][j]);
            }
            #pragma unroll
            for (int i = 0; i < 2; i++)
                #pragma unroll
                for (int j = 0; j < 2; j++)
                    wmma::store_matrix_sync(sO + (wr*32 + i*16)*OP + wc*32 + j*16,
                                            pacc[i][j], OP, wmma::mem_row_major);
        }
        __syncthreads();   // E

        // ---- accumulate PV into per-thread O registers ----
        #pragma unroll
        for (int rr = 0; rr < 8; rr++) {
            int row = warp*8 + rr;
            float4 pv = *(const float4*)(sO + row*OP + lane*4);
            o[rr][0] += pv.x; o[rr][1] += pv.y; o[rr][2] += pv.z; o[rr][3] += pv.w;
        }
    }

    #pragma unroll
    for (int rr = 0; rr < 8; rr++) {
        int qi = q0 + warp*8 + rr;
        float inv = 1.0f / l[rr];
        float4 v = make_float4(o[rr][0]*inv, o[rr][1]*inv, o[rr][2]*inv, o[rr][3]*inv);
        *(float4*)(O + ((size_t)((b*LL + qi)*NQH + h))*HD + lane*4) = v;
    }
}

// ---------------- silu(g) * u ----------------
__global__ void silu_mul_kernel(const float* __restrict__ g, const float* __restrict__ u,
                                float* __restrict__ out, int n4)
{
    int i = blockIdx.x * blockDim.x + threadIdx.x;
    if (i >= n4) return;
    float4 gv = ((const float4*)g)[i];
    float4 uv = ((const float4*)u)[i];
    float4 o;
    o.x = gv.x / (1.f + __expf(-gv.x)) * uv.x;
    o.y = gv.y / (1.f + __expf(-gv.y)) * uv.y;
    o.z = gv.z / (1.f + __expf(-gv.z)) * uv.z;
    o.w = gv.w / (1.f + __expf(-gv.w)) * uv.w;
    ((float4*)out)[i] = o;
}

// ---------------- launch ----------------
extern "C" void kernel_launch(void* const* d_in, const int* in_sizes, int n_in,
                              void* d_out, int out_size)
{
    const float* x   = (const float*)d_in[0];
    const float* ln1 = (const float*)d_in[1];
    const float* wq  = (const float*)d_in[2];
    const float* wk  = (const float*)d_in[3];
    const float* wv  = (const float*)d_in[4];
    const float* wo  = (const float*)d_in[5];
    const float* ln2 = (const float*)d_in[6];
    const float* wg  = (const float*)d_in[7];
    const float* wu  = (const float*)d_in[8];
    const float* wd  = (const float*)d_in[9];
    float* out = (float*)d_out;

    float *h, *q, *k, *v, *ctx, *x1, *h2, *g, *u;
    cudaGetSymbolAddress((void**)&h,   g_h);
    cudaGetSymbolAddress((void**)&q,   g_q);
    cudaGetSymbolAddress((void**)&k,   g_k);
    cudaGetSymbolAddress((void**)&v,   g_v);
    cudaGetSymbolAddress((void**)&ctx, g_ctx);
    cudaGetSymbolAddress((void**)&x1,  g_x1);
    cudaGetSymbolAddress((void**)&h2,  g_h2);
    cudaGetSymbolAddress((void**)&g,   g_g);
    cudaGetSymbolAddress((void**)&u,   g_u);

    cudaFuncSetAttribute(attn_kernel, cudaFuncAttributeMaxDynamicSharedMemorySize, ATTN_SMEM);
    cudaFuncSetAttribute(gemm_kernel, cudaFuncAttributeMaxDynamicSharedMemorySize, GEMM_SMEM);
    cudaFuncSetAttribute(qkv_kernel,  cudaFuncAttributeMaxDynamicSharedMemorySize, GEMM_SMEM);
    cudaFuncSetAttribute(gu_kernel,   cudaFuncAttributeMaxDynamicSharedMemorySize, GEMM_SMEM);

    // 1) rmsnorm1
    rmsnorm_kernel<<<ROWS, 256>>>(x, ln1, h);
    // 2) fused qkv projections (tensor cores)
    qkv_kernel<<<dim3(12, ROWS/128), 256, GEMM_SMEM>>>(h, wq, wk, wv, q, k, v);
    // 3) rope (in place)
    {
        int tq = ROWS * NQH * 64;
        rope_kernel<<<(tq + 255) / 256, 256>>>(q, NQH, tq);
        int tk = ROWS * NKVH * 64;
        rope_kernel<<<(tk + 255) / 256, 256>>>(k, NKVH, tk);
    }
    // 4) attention (wmma tf32)
    attn_kernel<<<dim3(LL / TQ, NQH, BB), 256, ATTN_SMEM>>>(q, k, v, ctx);
    // 5) output proj + residual
    gemm_kernel<<<dim3(DD/128, ROWS/128), 256, GEMM_SMEM>>>(ctx, wo, x, x1, DD, DD);
    // 6) rmsnorm2
    rmsnorm_kernel<<<ROWS, 256>>>(x1, ln2, h2);
    // 7) fused ffn gate+up
    gu_kernel<<<dim3(64, ROWS/128), 256, GEMM_SMEM>>>(h2, wg, wu, g, u);
    // 8) silu*mul
    {
        int n4 = ROWS * FFND / 4;
        silu_mul_kernel<<<(n4 + 255) / 256, 256>>>(g, u, g, n4);
    }
    // 9) down proj + residual -> out
    gemm_kernel<<<dim3(DD/128, ROWS/128), 256, GEMM_SMEM>>>(g, wd, x1, out, FFND, DD);
}

// round 6
// speedup vs baseline: 1.9811x; 1.0955x over previous
#include <cuda_runtime.h>
#include <cuda_bf16.h>
#include <mma.h>
#include <math.h>
#include <cstdint>

using namespace nvcuda;

// Problem constants
#define BB 2
#define LL 2048
#define DD 1024
#define NQH 8
#define NKVH 2
#define HD 128
#define FFND 4096
#define ROWS (BB*LL)            // 4096
#define EPSV 1.1920929e-07f

// ---------------- scratch (device globals; no allocs allowed) ----------------
__device__ float g_h  [ROWS*DD];        // rmsnorm1 out
__device__ float g_q  [ROWS*NQH*HD];    // q proj
__device__ float g_k  [ROWS*NKVH*HD];   // k proj
__device__ float g_v  [ROWS*NKVH*HD];   // v proj
__device__ float g_ctx[ROWS*NQH*HD];    // attention out
__device__ float g_x1 [ROWS*DD];        // post-attn residual stream
__device__ float g_h2 [ROWS*DD];        // rmsnorm2 out
__device__ float g_g  [ROWS*FFND];      // gate proj (reused for silu*u)
__device__ float g_u  [ROWS*FFND];      // up proj

// ---------------- RMSNorm ----------------
__global__ __launch_bounds__(256) void rmsnorm_kernel(
    const float* __restrict__ x, const float* __restrict__ w, float* __restrict__ out)
{
    int row = blockIdx.x;
    const float4* xr = (const float4*)(x + (size_t)row * DD);
    float4 v = xr[threadIdx.x];
    float s = v.x*v.x + v.y*v.y + v.z*v.z + v.w*v.w;
    #pragma unroll
    for (int off = 16; off; off >>= 1) s += __shfl_xor_sync(0xffffffffu, s, off);
    __shared__ float red[8];
    if ((threadIdx.x & 31) == 0) red[threadIdx.x >> 5] = s;
    __syncthreads();
    float tot = red[0]+red[1]+red[2]+red[3]+red[4]+red[5]+red[6]+red[7];
    float r = rsqrtf(tot * (1.0f/DD) + EPSV);
    const float4 wv = ((const float4*)w)[threadIdx.x];
    float4 o = make_float4(v.x*r*wv.x, v.y*r*wv.y, v.z*r*wv.z, v.w*r*wv.w);
    ((float4*)(out + (size_t)row * DD))[threadIdx.x] = o;
}

// ---------------- RoPE (in-place, q+k in one launch) ----------------
__global__ void rope_kernel(float* __restrict__ q, float* __restrict__ k, int total)
{
    int idx = blockIdx.x * blockDim.x + threadIdx.x;
    if (idx >= total) return;
    int d = idx & 63;
    int t = idx >> 6;
    int hh = t % (NQH + NKVH);
    int row = t / (NQH + NKVH);
    int pos = row & (LL - 1);
    float freq = powf(10000.0f, (float)d * (2.0f / HD));
    float rad = (float)pos / freq;
    float sn, cs;
    sincosf(rad, &sn, &cs);
    float* p = (hh < NQH) ? (q + ((size_t)row * NQH + hh) * HD)
                          : (k + ((size_t)row * NKVH + (hh - NQH)) * HD);
    float x1 = p[d], x2 = p[d + 64];
    p[d]      = x1*cs - x2*sn;
    p[d + 64] = x2*cs + x1*sn;
}

// ---------------- tf32 tensor-core GEMM core ----------------
// Block tile 128x128x32, 2-stage cp.async pipeline, 4 warps (64x64 warp tile)
#define GASZ (128*36)
#define GBSZ (32*132)
#define GEMM_SMEM ((2*GASZ + 2*GBSZ)*4)   // 70656 bytes

__device__ __forceinline__ void cp_async16(float* smem, const float* g)
{
    unsigned int s = (unsigned int)__cvta_generic_to_shared(smem);
    asm volatile("cp.async.cg.shared.global [%0], [%1], 16;\n" :: "r"(s), "l"(g));
}

__device__ __forceinline__ void gemm_stage_load(
    float* As, float* Bs, const float* A, const float* B,
    int K, int ldb, int bm0, int col0, int k0, int tid)
{
    #pragma unroll
    for (int p = 0; p < 8; p++) {
        int idx = p * 128 + tid;
        int row = idx >> 3, c4 = (idx & 7) * 4;
        cp_async16(As + row*36 + c4, A + (size_t)(bm0 + row)*K + k0 + c4);
    }
    #pragma unroll
    for (int p = 0; p < 8; p++) {
        int idx = p * 128 + tid;
        int br = idx >> 5, bc4 = (idx & 31) * 4;
        cp_async16(Bs + br*132 + bc4, B + (size_t)(k0 + br)*ldb + col0 + bc4);
    }
    asm volatile("cp.async.commit_group;\n" ::);
}

__device__ __forceinline__ void gemm_core(
    const float* __restrict__ A, const float* __restrict__ B,
    const float* __restrict__ Res, float* __restrict__ C,
    int K, int ldb, int ldc, int bm0, int col0)
{
    extern __shared__ float smem[];
    float* As = smem;              // [2][128][36]
    float* Bs = smem + 2*GASZ;     // [2][32][132]

    int tid  = threadIdx.x;
    int warp = tid >> 5;
    int wm = warp & 1;             // 0..1 -> 64-row slab
    int wn = warp >> 1;            // 0..1 -> 64-col slab

    wmma::fragment<wmma::accumulator, 16,16,8, float> acc[4][4];
    #pragma unroll
    for (int i = 0; i < 4; i++)
        #pragma unroll
        for (int j = 0; j < 4; j++)
            wmma::fill_fragment(acc[i][j], 0.0f);

    int nk = K >> 5;

    gemm_stage_load(As, Bs, A, B, K, ldb, bm0, col0, 0, tid);

    for (int kt = 0; kt < nk; kt++) {
        asm volatile("cp.async.wait_group 0;\n" ::);
        __syncthreads();

        if (kt + 1 < nk) {
            int s = (kt + 1) & 1;
            gemm_stage_load(As + s*GASZ, Bs + s*GBSZ, A, B, K, ldb, bm0, col0, (kt + 1) << 5, tid);
        }

        int s = kt & 1;
        #pragma unroll
        for (int ks = 0; ks < 4; ks++) {
            wmma::fragment<wmma::matrix_a, 16,16,8, wmma::precision::tf32, wmma::row_major> af[4];
            wmma::fragment<wmma::matrix_b, 16,16,8, wmma::precision::tf32, wmma::row_major> bf[4];
            #pragma unroll
            for (int i = 0; i < 4; i++)
                wmma::load_matrix_sync(af[i], As + s*GASZ + (wm*64 + i*16)*36 + ks*8, 36);
            #pragma unroll
            for (int j = 0; j < 4; j++)
                wmma::load_matrix_sync(bf[j], Bs + s*GBSZ + (ks*8)*132 + wn*64 + j*16, 132);
            #pragma unroll
            for (int i = 0; i < 4; i++)
                #pragma unroll
                for (int j = 0; j < 4; j++)
                    wmma::mma_sync(acc[i][j], af[i], bf[j], acc[i][j]);
        }
    }

    // epilogue (+ optional residual)
    #pragma unroll
    for (int i = 0; i < 4; i++) {
        int r0 = bm0 + wm*64 + i*16;
        #pragma unroll
        for (int j = 0; j < 4; j++) {
            int c0 = col0 + wn*64 + j*16;
            if (Res) {
                wmma::fragment<wmma::accumulator, 16,16,8, float> rf;
                wmma::load_matrix_sync(rf, Res + (size_t)r0*ldc + c0, ldc, wmma::mem_row_major);
                #pragma unroll
                for (int e = 0; e < rf.num_elements; e++)
                    acc[i][j].x[e] += rf.x[e];
            }
            wmma::store_matrix_sync(C + (size_t)r0*ldc + c0, acc[i][j], ldc, wmma::mem_row_major);
        }
    }
}

// generic GEMM: C = A @ B [+ Res], N = ldb = ldc
__global__ __launch_bounds__(128) void gemm_kernel(
    const float* __restrict__ A, const float* __restrict__ B,
    const float* __restrict__ Res, float* __restrict__ C, int K, int N)
{
    gemm_core(A, B, Res, C, K, N, N, blockIdx.y * 128, blockIdx.x * 128);
}

// fused QKV: one launch covering wq (8 col-blocks), wk (2), wv (2)
__global__ __launch_bounds__(128) void qkv_kernel(
    const float* __restrict__ h,
    const float* __restrict__ wq, const float* __restrict__ wk, const float* __restrict__ wv,
    float* __restrict__ q, float* __restrict__ k, float* __restrict__ v)
{
    int bn = blockIdx.x;
    const float* B; float* C; int ldn; int c0;
    if (bn < 8)       { B = wq; C = q; ldn = NQH*HD;  c0 = bn * 128; }
    else if (bn < 10) { B = wk; C = k; ldn = NKVH*HD; c0 = (bn - 8) * 128; }
    else              { B = wv; C = v; ldn = NKVH*HD; c0 = (bn - 10) * 128; }
    gemm_core(h, B, nullptr, C, DD, ldn, ldn, blockIdx.y * 128, c0);
}

// fused gate+up: bn<32 -> wg, else wu
__global__ __launch_bounds__(128) void gu_kernel(
    const float* __restrict__ h2,
    const float* __restrict__ wg, const float* __restrict__ wu,
    float* __restrict__ g, float* __restrict__ u)
{
    int bn = blockIdx.x;
    const float* B = (bn < 32) ? wg : wu;
    float* C       = (bn < 32) ? g  : u;
    int c0 = (bn & 31) * 128;
    gemm_core(h2, B, nullptr, C, DD, FFND, FFND, blockIdx.y * 128, c0);
}

// ---------------- Flash attention: wmma tf32 QK^T and PV, scalar fp32 softmax ----------------
#define TQ 64
#define TK 64
#define SP 72                              // S/P tile pitch
#define OP 132                             // PV tile pitch
// sQ(64*128) + sK(64*128) + sV(64*128) + sS(64*72) + sO(64*132)
#define ATTN_SMEM ((3*TQ*HD + TQ*SP + TQ*OP) * 4)   // 150528 bytes

__global__ __launch_bounds__(256) void attn_kernel(
    const float* __restrict__ Q, const float* __restrict__ K,
    const float* __restrict__ V, float* __restrict__ O)
{
    extern __shared__ float sm[];
    float* sQ = sm;                     // [64][128]
    float* sK = sQ + TQ * HD;           // [64][128]
    float* sV = sK + TK * HD;           // [64][128]
    float* sS = sV + TK * HD;           // [64][72]
    float* sO = sS + TQ * SP;           // [64][132]

    int qt = blockIdx.x, h = blockIdx.y, b = blockIdx.z;
    int kh = h >> 2;
    int tid = threadIdx.x;
    int warp = tid >> 5, lane = tid & 31;
    int q0 = qt * TQ;
    int wr = warp & 1, wc = warp >> 1;  // 2x4 warp grid for wmma steps

    // load Q tile
    #pragma unroll
    for (int it = 0; it < (TQ * HD / 4) / 256; it++) {
        int idx = it * 256 + tid;
        int r = idx >> 5, c4 = idx & 31;
        float4 v = *(const float4*)(Q + ((size_t)((b*LL + q0 + r)*NQH + h))*HD + c4*4);
        *(float4*)(sQ + r * HD + c4 * 4) = v;
    }

    float o[8][4], m[8], l[8];
    #pragma unroll
    for (int r = 0; r < 8; r++) {
        m[r] = -1e30f; l[r] = 0.f;
        o[r][0] = o[r][1] = o[r][2] = o[r][3] = 0.f;
    }
    const float scale = 0.08838834764831845f;

    for (int kt = 0; kt <= qt; kt++) {
        int kb = kt * TK;
        __syncthreads();   // A: protect sK/sV/sO reuse
        #pragma unroll
        for (int it = 0; it < (TK * HD / 4) / 256; it++) {
            int idx = it * 256 + tid;
            int j = idx >> 5, c4 = idx & 31;
            float4 kv = *(const float4*)(K + ((size_t)((b*LL + kb + j)*NKVH + kh))*HD + c4*4);
            *(float4*)(sK + j * HD + c4 * 4) = kv;
            float4 vv = *(const float4*)(V + ((size_t)((b*LL + kb + j)*NKVH + kh))*HD + c4*4);
            *(float4*)(sV + j * HD + c4 * 4) = vv;
        }
        __syncthreads();   // B

        // ---- S = Q @ K^T (64x64), warp = 32 rows x 16 cols ----
        {
            wmma::fragment<wmma::accumulator, 16,16,8, float> sacc[2];
            wmma::fill_fragment(sacc[0], 0.0f);
            wmma::fill_fragment(sacc[1], 0.0f);
            #pragma unroll
            for (int kk = 0; kk < 16; kk++) {
                wmma::fragment<wmma::matrix_b, 16,16,8, wmma::precision::tf32, wmma::col_major> bf;
                wmma::load_matrix_sync(bf, sK + wc*16*HD + kk*8, HD);
                #pragma unroll
                for (int i = 0; i < 2; i++) {
                    wmma::fragment<wmma::matrix_a, 16,16,8, wmma::precision::tf32, wmma::row_major> af;
                    wmma::load_matrix_sync(af, sQ + (wr*32 + i*16)*HD + kk*8, HD);
                    wmma::mma_sync(sacc[i], af, bf, sacc[i]);
                }
            }
            wmma::store_matrix_sync(sS + (wr*32 +  0)*SP + wc*16, sacc[0], SP, wmma::mem_row_major);
            wmma::store_matrix_sync(sS + (wr*32 + 16)*SP + wc*16, sacc[1], SP, wmma::mem_row_major);
        }
        __syncthreads();   // C

        // ---- online softmax: warp owns rows warp*8 .. warp*8+7 ----
        #pragma unroll
        for (int rr = 0; rr < 8; rr++) {
            int row = warp*8 + rr;
            int qi = q0 + row;
            float s1 = sS[row*SP + lane];
            float s2 = sS[row*SP + lane + 32];
            s1 = (kb + lane      <= qi) ? s1 * scale : -1e30f;
            s2 = (kb + lane + 32 <= qi) ? s2 * scale : -1e30f;
            float mx = fmaxf(s1, s2);
            #pragma unroll
            for (int off = 16; off; off >>= 1)
                mx = fmaxf(mx, __shfl_xor_sync(0xffffffffu, mx, off));
            float mnew = fmaxf(m[rr], mx);
            float p1 = __expf(s1 - mnew);
            float p2 = __expf(s2 - mnew);
            float ps = p1 + p2;
            #pragma unroll
            for (int off = 16; off; off >>= 1)
                ps += __shfl_xor_sync(0xffffffffu, ps, off);
            float alpha = __expf(m[rr] - mnew);
            m[rr] = mnew;
            l[rr] = l[rr] * alpha + ps;
            o[rr][0] *= alpha; o[rr][1] *= alpha; o[rr][2] *= alpha; o[rr][3] *= alpha;
            sS[row*SP + lane]      = p1;
            sS[row*SP + lane + 32] = p2;
        }
        __syncthreads();   // D

        // ---- PV = P(64x64) @ V(64x128), warp = 32 rows x 32 cols ----
        {
            wmma::fragment<wmma::accumulator, 16,16,8, float> pacc[2][2];
            #pragma unroll
            for (int i = 0; i < 2; i++)
                #pragma unroll
                for (int j = 0; j < 2; j++)
                    wmma::fill_fragment(pacc[i][j], 0.0f);
            #pragma unroll
            for (int kk = 0; kk < 8; kk++) {
                wmma::fragment<wmma::matrix_a, 16,16,8, wmma::precision::tf32, wmma::row_major> af[2];
                wmma::fragment<wmma::matrix_b, 16,16,8, wmma::precision::tf32, wmma::row_major> bf[2];
                #pragma unroll
                for (int i = 0; i < 2; i++)
                    wmma::load_matrix_sync(af[i], sS + (wr*32 + i*16)*SP + kk*8, SP);
                #pragma unroll
                for (int j = 0; j < 2; j++)
                    wmma::load_matrix_sync(bf[j], sV + (kk*8)*HD + wc*32 + j*16, HD);
                #pragma unroll
                for (int i = 0; i < 2; i++)
                    #pragma unroll
                    for (int j = 0; j < 2; j++)
                        wmma::mma_sync(pacc[i][j], af[i], bf[j], pacc[i][j]);
            }
            #pragma unroll
            for (int i = 0; i < 2; i++)
                #pragma unroll
                for (int j = 0; j < 2; j++)
                    wmma::store_matrix_sync(sO + (wr*32 + i*16)*OP + wc*32 + j*16,
                                            pacc[i][j], OP, wmma::mem_row_major);
        }
        __syncthreads();   // E

        // ---- accumulate PV into per-thread O registers ----
        #pragma unroll
        for (int rr = 0; rr < 8; rr++) {
            int row = warp*8 + rr;
            float4 pv = *(const float4*)(sO + row*OP + lane*4);
            o[rr][0] += pv.x; o[rr][1] += pv.y; o[rr][2] += pv.z; o[rr][3] += pv.w;
        }
    }

    #pragma unroll
    for (int rr = 0; rr < 8; rr++) {
        int qi = q0 + warp*8 + rr;
        float inv = 1.0f / l[rr];
        float4 v = make_float4(o[rr][0]*inv, o[rr][1]*inv, o[rr][2]*inv, o[rr][3]*inv);
        *(float4*)(O + ((size_t)((b*LL + qi)*NQH + h))*HD + lane*4) = v;
    }
}

// ---------------- silu(g) * u ----------------
__global__ void silu_mul_kernel(const float* __restrict__ g, const float* __restrict__ u,
                                float* __restrict__ out, int n4)
{
    int i = blockIdx.x * blockDim.x + threadIdx.x;
    if (i >= n4) return;
    float4 gv = ((const float4*)g)[i];
    float4 uv = ((const float4*)u)[i];
    float4 o;
    o.x = gv.x / (1.f + __expf(-gv.x)) * uv.x;
    o.y = gv.y / (1.f + __expf(-gv.y)) * uv.y;
    o.z = gv.z / (1.f + __expf(-gv.z)) * uv.z;
    o.w = gv.w / (1.f + __expf(-gv.w)) * uv.w;
    ((float4*)out)[i] = o;
}

// ---------------- launch ----------------
extern "C" void kernel_launch(void* const* d_in, const int* in_sizes, int n_in,
                              void* d_out, int out_size)
{
    const float* x   = (const float*)d_in[0];
    const float* ln1 = (const float*)d_in[1];
    const float* wq  = (const float*)d_in[2];
    const float* wk  = (const float*)d_in[3];
    const float* wv  = (const float*)d_in[4];
    const float* wo  = (const float*)d_in[5];
    const float* ln2 = (const float*)d_in[6];
    const float* wg  = (const float*)d_in[7];
    const float* wu  = (const float*)d_in[8];
    const float* wd  = (const float*)d_in[9];
    float* out = (float*)d_out;

    float *h, *q, *k, *v, *ctx, *x1, *h2, *g, *u;
    cudaGetSymbolAddress((void**)&h,   g_h);
    cudaGetSymbolAddress((void**)&q,   g_q);
    cudaGetSymbolAddress((void**)&k,   g_k);
    cudaGetSymbolAddress((void**)&v,   g_v);
    cudaGetSymbolAddress((void**)&ctx, g_ctx);
    cudaGetSymbolAddress((void**)&x1,  g_x1);
    cudaGetSymbolAddress((void**)&h2,  g_h2);
    cudaGetSymbolAddress((void**)&g,   g_g);
    cudaGetSymbolAddress((void**)&u,   g_u);

    cudaFuncSetAttribute(attn_kernel, cudaFuncAttributeMaxDynamicSharedMemorySize, ATTN_SMEM);
    cudaFuncSetAttribute(gemm_kernel, cudaFuncAttributeMaxDynamicSharedMemorySize, GEMM_SMEM);
    cudaFuncSetAttribute(qkv_kernel,  cudaFuncAttributeMaxDynamicSharedMemorySize, GEMM_SMEM);
    cudaFuncSetAttribute(gu_kernel,   cudaFuncAttributeMaxDynamicSharedMemorySize, GEMM_SMEM);

    // 1) rmsnorm1
    rmsnorm_kernel<<<ROWS, 256>>>(x, ln1, h);
    // 2) fused qkv projections (tensor cores)
    qkv_kernel<<<dim3(12, ROWS/128), 128, GEMM_SMEM>>>(h, wq, wk, wv, q, k, v);
    // 3) rope (q + k in one launch, in place)
    {
        int t = ROWS * (NQH + NKVH) * 64;
        rope_kernel<<<(t + 255) / 256, 256>>>(q, k, t);
    }
    // 4) attention (wmma tf32)
    attn_kernel<<<dim3(LL / TQ, NQH, BB), 256, ATTN_SMEM>>>(q, k, v, ctx);
    // 5) output proj + residual
    gemm_kernel<<<dim3(DD/128, ROWS/128), 128, GEMM_SMEM>>>(ctx, wo, x, x1, DD, DD);
    // 6) rmsnorm2
    rmsnorm_kernel<<<ROWS, 256>>>(x1, ln2, h2);
    // 7) fused ffn gate+up
    gu_kernel<<<dim3(64, ROWS/128), 128, GEMM_SMEM>>>(h2, wg, wu, g, u);
    // 8) silu*mul
    {
        int n4 = ROWS * FFND / 4;
        silu_mul_kernel<<<(n4 + 255) / 256, 256>>>(g, u, g, n4);
    }
    // 9) down proj + residual -> out
    gemm_kernel<<<dim3(DD/128, ROWS/128), 128, GEMM_SMEM>>>(g, wd, x1, out, FFND, DD);
}

// round 7
// speedup vs baseline: 2.8694x; 1.4484x over previous
#include <cuda_runtime.h>
#include <cuda_fp16.h>
#include <mma.h>
#include <math.h>
#include <cstdint>

using namespace nvcuda;

// Problem constants
#define BB 2
#define LL 2048
#define DD 1024
#define NQH 8
#define NKVH 2
#define HD 128
#define FFND 4096
#define ROWS (BB*LL)            // 4096
#define EPSV 1.1920929e-07f

// ---------------- scratch (device globals; no allocs allowed) ----------------
__device__ float g_h  [ROWS*DD];
__device__ float g_q  [ROWS*NQH*HD];
__device__ float g_k  [ROWS*NKVH*HD];
__device__ float g_v  [ROWS*NKVH*HD];
__device__ float g_ctx[ROWS*NQH*HD];
__device__ float g_x1 [ROWS*DD];
__device__ float g_h2 [ROWS*DD];
__device__ float g_g  [ROWS*FFND];
__device__ float g_u  [ROWS*FFND];

// ---------------- RMSNorm ----------------
__global__ __launch_bounds__(256) void rmsnorm_kernel(
    const float* __restrict__ x, const float* __restrict__ w, float* __restrict__ out)
{
    int row = blockIdx.x;
    const float4* xr = (const float4*)(x + (size_t)row * DD);
    float4 v = xr[threadIdx.x];
    float s = v.x*v.x + v.y*v.y + v.z*v.z + v.w*v.w;
    #pragma unroll
    for (int off = 16; off; off >>= 1) s += __shfl_xor_sync(0xffffffffu, s, off);
    __shared__ float red[8];
    if ((threadIdx.x & 31) == 0) red[threadIdx.x >> 5] = s;
    __syncthreads();
    float tot = red[0]+red[1]+red[2]+red[3]+red[4]+red[5]+red[6]+red[7];
    float r = rsqrtf(tot * (1.0f/DD) + EPSV);
    const float4 wv = ((const float4*)w)[threadIdx.x];
    float4 o = make_float4(v.x*r*wv.x, v.y*r*wv.y, v.z*r*wv.z, v.w*r*wv.w);
    ((float4*)(out + (size_t)row * DD))[threadIdx.x] = o;
}

// ---------------- RoPE (in-place, q+k in one launch) ----------------
__global__ void rope_kernel(float* __restrict__ q, float* __restrict__ k, int total)
{
    int idx = blockIdx.x * blockDim.x + threadIdx.x;
    if (idx >= total) return;
    int d = idx & 63;
    int t = idx >> 6;
    int hh = t % (NQH + NKVH);
    int row = t / (NQH + NKVH);
    int pos = row & (LL - 1);
    float freq = powf(10000.0f, (float)d * (2.0f / HD));
    float rad = (float)pos / freq;
    float sn, cs;
    sincosf(rad, &sn, &cs);
    float* p = (hh < NQH) ? (q + ((size_t)row * NQH + hh) * HD)
                          : (k + ((size_t)row * NKVH + (hh - NQH)) * HD);
    float x1 = p[d], x2 = p[d + 64];
    p[d]      = x1*cs - x2*sn;
    p[d + 64] = x2*cs + x1*sn;
}

// ---------------- tf32 tensor-core GEMM core ----------------
#define GASZ (128*36)
#define GBSZ (32*132)
#define GEMM_SMEM ((2*GASZ + 2*GBSZ)*4)   // 70656 bytes

__device__ __forceinline__ void cp_async16(float* smem, const float* g)
{
    unsigned int s = (unsigned int)__cvta_generic_to_shared(smem);
    asm volatile("cp.async.cg.shared.global [%0], [%1], 16;\n" :: "r"(s), "l"(g));
}

__device__ __forceinline__ void gemm_stage_load(
    float* As, float* Bs, const float* A, const float* B,
    int K, int ldb, int bm0, int col0, int k0, int tid)
{
    #pragma unroll
    for (int p = 0; p < 8; p++) {
        int idx = p * 128 + tid;
        int row = idx >> 3, c4 = (idx & 7) * 4;
        cp_async16(As + row*36 + c4, A + (size_t)(bm0 + row)*K + k0 + c4);
    }
    #pragma unroll
    for (int p = 0; p < 8; p++) {
        int idx = p * 128 + tid;
        int br = idx >> 5, bc4 = (idx & 31) * 4;
        cp_async16(Bs + br*132 + bc4, B + (size_t)(k0 + br)*ldb + col0 + bc4);
    }
    asm volatile("cp.async.commit_group;\n" ::);
}

__device__ __forceinline__ void gemm_core(
    const float* __restrict__ A, const float* __restrict__ B,
    const float* __restrict__ Res, float* __restrict__ C,
    int K, int ldb, int ldc, int bm0, int col0)
{
    extern __shared__ float smem[];
    float* As = smem;              // [2][128][36]
    float* Bs = smem + 2*GASZ;     // [2][32][132]

    int tid  = threadIdx.x;
    int warp = tid >> 5;
    int wm = warp & 1;
    int wn = warp >> 1;

    wmma::fragment<wmma::accumulator, 16,16,8, float> acc[4][4];
    #pragma unroll
    for (int i = 0; i < 4; i++)
        #pragma unroll
        for (int j = 0; j < 4; j++)
            wmma::fill_fragment(acc[i][j], 0.0f);

    int nk = K >> 5;

    gemm_stage_load(As, Bs, A, B, K, ldb, bm0, col0, 0, tid);

    for (int kt = 0; kt < nk; kt++) {
        asm volatile("cp.async.wait_group 0;\n" ::);
        __syncthreads();

        if (kt + 1 < nk) {
            int s = (kt + 1) & 1;
            gemm_stage_load(As + s*GASZ, Bs + s*GBSZ, A, B, K, ldb, bm0, col0, (kt + 1) << 5, tid);
        }

        int s = kt & 1;
        #pragma unroll
        for (int ks = 0; ks < 4; ks++) {
            wmma::fragment<wmma::matrix_a, 16,16,8, wmma::precision::tf32, wmma::row_major> af[4];
            wmma::fragment<wmma::matrix_b, 16,16,8, wmma::precision::tf32, wmma::row_major> bf[4];
            #pragma unroll
            for (int i = 0; i < 4; i++)
                wmma::load_matrix_sync(af[i], As + s*GASZ + (wm*64 + i*16)*36 + ks*8, 36);
            #pragma unroll
            for (int j = 0; j < 4; j++)
                wmma::load_matrix_sync(bf[j], Bs + s*GBSZ + (ks*8)*132 + wn*64 + j*16, 132);
            #pragma unroll
            for (int i = 0; i < 4; i++)
                #pragma unroll
                for (int j = 0; j < 4; j++)
                    wmma::mma_sync(acc[i][j], af[i], bf[j], acc[i][j]);
        }
    }

    #pragma unroll
    for (int i = 0; i < 4; i++) {
        int r0 = bm0 + wm*64 + i*16;
        #pragma unroll
        for (int j = 0; j < 4; j++) {
            int c0 = col0 + wn*64 + j*16;
            if (Res) {
                wmma::fragment<wmma::accumulator, 16,16,8, float> rf;
                wmma::load_matrix_sync(rf, Res + (size_t)r0*ldc + c0, ldc, wmma::mem_row_major);
                #pragma unroll
                for (int e = 0; e < rf.num_elements; e++)
                    acc[i][j].x[e] += rf.x[e];
            }
            wmma::store_matrix_sync(C + (size_t)r0*ldc + c0, acc[i][j], ldc, wmma::mem_row_major);
        }
    }
}

__global__ __launch_bounds__(128) void gemm_kernel(
    const float* __restrict__ A, const float* __restrict__ B,
    const float* __restrict__ Res, float* __restrict__ C, int K, int N)
{
    gemm_core(A, B, Res, C, K, N, N, blockIdx.y * 128, blockIdx.x * 128);
}

__global__ __launch_bounds__(128) void qkv_kernel(
    const float* __restrict__ h,
    const float* __restrict__ wq, const float* __restrict__ wk, const float* __restrict__ wv,
    float* __restrict__ q, float* __restrict__ k, float* __restrict__ v)
{
    int bn = blockIdx.x;
    const float* B; float* C; int ldn; int c0;
    if (bn < 8)       { B = wq; C = q; ldn = NQH*HD;  c0 = bn * 128; }
    else if (bn < 10) { B = wk; C = k; ldn = NKVH*HD; c0 = (bn - 8) * 128; }
    else              { B = wv; C = v; ldn = NKVH*HD; c0 = (bn - 10) * 128; }
    gemm_core(h, B, nullptr, C, DD, ldn, ldn, blockIdx.y * 128, c0);
}

__global__ __launch_bounds__(128) void gu_kernel(
    const float* __restrict__ h2,
    const float* __restrict__ wg, const float* __restrict__ wu,
    float* __restrict__ g, float* __restrict__ u)
{
    int bn = blockIdx.x;
    const float* B = (bn < 32) ? wg : wu;
    float* C       = (bn < 32) ? g  : u;
    int c0 = (bn & 31) * 128;
    gemm_core(h2, B, nullptr, C, DD, FFND, FFND, blockIdx.y * 128, c0);
}

// ---------------- Flash attention: fp16 wmma QK^T and PV, fp32 softmax ----------------
#define TQ 64
#define TK 64
#define HP 136                 // half pitch for Q/K/V tiles
#define SP 72                  // fp32 S pitch
#define PP 80                  // half P pitch
#define OP 132                 // fp32 PV pitch
// bytes: 3*64*136*2 + 64*72*4 + 64*80*2 + 64*132*4 = 52224 + 18432 + 10240 + 33792
#define ATTN_SMEM (3*TQ*HP*2 + TQ*SP*4 + TQ*PP*2 + TQ*OP*4)   // 114688 bytes

__global__ __launch_bounds__(256, 2) void attn_kernel(
    const float* __restrict__ Q, const float* __restrict__ K,
    const float* __restrict__ V, float* __restrict__ O)
{
    extern __shared__ char smraw[];
    half*  hQ = (half*)smraw;                 // [64][136]
    half*  hK = hQ + TQ * HP;                 // [64][136]
    half*  hV = hK + TQ * HP;                 // [64][136]
    float* sS = (float*)(hV + TQ * HP);       // [64][72]
    half*  sP = (half*)(sS + TQ * SP);        // [64][80]
    float* sO = (float*)(sP + TQ * PP);       // [64][132]

    int qt = (gridDim.x - 1) - blockIdx.x;    // heavy tiles first
    int h = blockIdx.y, b = blockIdx.z;
    int kh = h >> 2;
    int tid = threadIdx.x;
    int warp = tid >> 5, lane = tid & 31;
    int q0 = qt * TQ;
    int wr = warp & 1, wc = warp >> 1;

    // load Q tile (fp32 -> fp16)
    #pragma unroll
    for (int it = 0; it < (TQ * HD / 4) / 256; it++) {
        int idx = it * 256 + tid;
        int r = idx >> 5, c4 = idx & 31;
        float4 v = *(const float4*)(Q + ((size_t)((b*LL + q0 + r)*NQH + h))*HD + c4*4);
        half2 lo = __floats2half2_rn(v.x, v.y);
        half2 hi = __floats2half2_rn(v.z, v.w);
        *(half2*)(hQ + r * HP + c4 * 4)     = lo;
        *(half2*)(hQ + r * HP + c4 * 4 + 2) = hi;
    }

    float o[8][4], m[8], l[8];
    #pragma unroll
    for (int r = 0; r < 8; r++) {
        m[r] = -1e30f; l[r] = 0.f;
        o[r][0] = o[r][1] = o[r][2] = o[r][3] = 0.f;
    }
    const float scale = 0.08838834764831845f;

    for (int kt = 0; kt <= qt; kt++) {
        int kb = kt * TK;
        __syncthreads();   // A
        #pragma unroll
        for (int it = 0; it < (TK * HD / 4) / 256; it++) {
            int idx = it * 256 + tid;
            int j = idx >> 5, c4 = idx & 31;
            float4 kv = *(const float4*)(K + ((size_t)((b*LL + kb + j)*NKVH + kh))*HD + c4*4);
            *(half2*)(hK + j * HP + c4*4)     = __floats2half2_rn(kv.x, kv.y);
            *(half2*)(hK + j * HP + c4*4 + 2) = __floats2half2_rn(kv.z, kv.w);
            float4 vv = *(const float4*)(V + ((size_t)((b*LL + kb + j)*NKVH + kh))*HD + c4*4);
            *(half2*)(hV + j * HP + c4*4)     = __floats2half2_rn(vv.x, vv.y);
            *(half2*)(hV + j * HP + c4*4 + 2) = __floats2half2_rn(vv.z, vv.w);
        }
        __syncthreads();   // B

        // ---- S = Q @ K^T (64x64), warp = 32 rows x 16 cols, k=16 per mma ----
        {
            wmma::fragment<wmma::accumulator, 16,16,16, float> sacc[2];
            wmma::fill_fragment(sacc[0], 0.0f);
            wmma::fill_fragment(sacc[1], 0.0f);
            #pragma unroll
            for (int kk = 0; kk < 8; kk++) {
                wmma::fragment<wmma::matrix_b, 16,16,16, half, wmma::col_major> bf;
                wmma::load_matrix_sync(bf, hK + (wc*16)*HP + kk*16, HP);
                #pragma unroll
                for (int i = 0; i < 2; i++) {
                    wmma::fragment<wmma::matrix_a, 16,16,16, half, wmma::row_major> af;
                    wmma::load_matrix_sync(af, hQ + (wr*32 + i*16)*HP + kk*16, HP);
                    wmma::mma_sync(sacc[i], af, bf, sacc[i]);
                }
            }
            wmma::store_matrix_sync(sS + (wr*32 +  0)*SP + wc*16, sacc[0], SP, wmma::mem_row_major);
            wmma::store_matrix_sync(sS + (wr*32 + 16)*SP + wc*16, sacc[1], SP, wmma::mem_row_major);
        }
        __syncthreads();   // C

        // ---- online softmax: warp owns rows warp*8 .. warp*8+7 ----
        #pragma unroll
        for (int rr = 0; rr < 8; rr++) {
            int row = warp*8 + rr;
            int qi = q0 + row;
            float s1 = sS[row*SP + lane];
            float s2 = sS[row*SP + lane + 32];
            s1 = (kb + lane      <= qi) ? s1 * scale : -1e30f;
            s2 = (kb + lane + 32 <= qi) ? s2 * scale : -1e30f;
            float mx = fmaxf(s1, s2);
            #pragma unroll
            for (int off = 16; off; off >>= 1)
                mx = fmaxf(mx, __shfl_xor_sync(0xffffffffu, mx, off));
            float mnew = fmaxf(m[rr], mx);
            float p1 = __expf(s1 - mnew);
            float p2 = __expf(s2 - mnew);
            float ps = p1 + p2;
            #pragma unroll
            for (int off = 16; off; off >>= 1)
                ps += __shfl_xor_sync(0xffffffffu, ps, off);
            float alpha = __expf(m[rr] - mnew);
            m[rr] = mnew;
            l[rr] = l[rr] * alpha + ps;
            o[rr][0] *= alpha; o[rr][1] *= alpha; o[rr][2] *= alpha; o[rr][3] *= alpha;
            sP[row*PP + lane]      = __float2half(p1);
            sP[row*PP + lane + 32] = __float2half(p2);
        }
        __syncthreads();   // D

        // ---- PV = P(64x64) @ V(64x128), warp = 32 rows x 32 cols ----
        {
            wmma::fragment<wmma::accumulator, 16,16,16, float> pacc[2][2];
            #pragma unroll
            for (int i = 0; i < 2; i++)
                #pragma unroll
                for (int j = 0; j < 2; j++)
                    wmma::fill_fragment(pacc[i][j], 0.0f);
            #pragma unroll
            for (int kk = 0; kk < 4; kk++) {
                wmma::fragment<wmma::matrix_a, 16,16,16, half, wmma::row_major> af[2];
                wmma::fragment<wmma::matrix_b, 16,16,16, half, wmma::row_major> bf[2];
                #pragma unroll
                for (int i = 0; i < 2; i++)
                    wmma::load_matrix_sync(af[i], sP + (wr*32 + i*16)*PP + kk*16, PP);
                #pragma unroll
                for (int j = 0; j < 2; j++)
                    wmma::load_matrix_sync(bf[j], hV + (kk*16)*HP + wc*32 + j*16, HP);
                #pragma unroll
                for (int i = 0; i < 2; i++)
                    #pragma unroll
                    for (int j = 0; j < 2; j++)
                        wmma::mma_sync(pacc[i][j], af[i], bf[j], pacc[i][j]);
            }
            #pragma unroll
            for (int i = 0; i < 2; i++)
                #pragma unroll
                for (int j = 0; j < 2; j++)
                    wmma::store_matrix_sync(sO + (wr*32 + i*16)*OP + wc*32 + j*16,
                                            pacc[i][j], OP, wmma::mem_row_major);
        }
        __syncthreads();   // E

        #pragma unroll
        for (int rr = 0; rr < 8; rr++) {
            int row = warp*8 + rr;
            float4 pv = *(const float4*)(sO + row*OP + lane*4);
            o[rr][0] += pv.x; o[rr][1] += pv.y; o[rr][2] += pv.z; o[rr][3] += pv.w;
        }
    }

    #pragma unroll
    for (int rr = 0; rr < 8; rr++) {
        int qi = q0 + warp*8 + rr;
        float inv = 1.0f / l[rr];
        float4 v = make_float4(o[rr][0]*inv, o[rr][1]*inv, o[rr][2]*inv, o[rr][3]*inv);
        *(float4*)(O + ((size_t)((b*LL + qi)*NQH + h))*HD + lane*4) = v;
    }
}

// ---------------- silu(g) * u ----------------
__global__ void silu_mul_kernel(const float* __restrict__ g, const float* __restrict__ u,
                                float* __restrict__ out, int n4)
{
    int i = blockIdx.x * blockDim.x + threadIdx.x;
    if (i >= n4) return;
    float4 gv = ((const float4*)g)[i];
    float4 uv = ((const float4*)u)[i];
    float4 o;
    o.x = gv.x / (1.f + __expf(-gv.x)) * uv.x;
    o.y = gv.y / (1.f + __expf(-gv.y)) * uv.y;
    o.z = gv.z / (1.f + __expf(-gv.z)) * uv.z;
    o.w = gv.w / (1.f + __expf(-gv.w)) * uv.w;
    ((float4*)out)[i] = o;
}

// ---------------- launch ----------------
extern "C" void kernel_launch(void* const* d_in, const int* in_sizes, int n_in,
                              void* d_out, int out_size)
{
    const float* x   = (const float*)d_in[0];
    const float* ln1 = (const float*)d_in[1];
    const float* wq  = (const float*)d_in[2];
    const float* wk  = (const float*)d_in[3];
    const float* wv  = (const float*)d_in[4];
    const float* wo  = (const float*)d_in[5];
    const float* ln2 = (const float*)d_in[6];
    const float* wg  = (const float*)d_in[7];
    const float* wu  = (const float*)d_in[8];
    const float* wd  = (const float*)d_in[9];
    float* out = (float*)d_out;

    float *h, *q, *k, *v, *ctx, *x1, *h2, *g, *u;
    cudaGetSymbolAddress((void**)&h,   g_h);
    cudaGetSymbolAddress((void**)&q,   g_q);
    cudaGetSymbolAddress((void**)&k,   g_k);
    cudaGetSymbolAddress((void**)&v,   g_v);
    cudaGetSymbolAddress((void**)&ctx, g_ctx);
    cudaGetSymbolAddress((void**)&x1,  g_x1);
    cudaGetSymbolAddress((void**)&h2,  g_h2);
    cudaGetSymbolAddress((void**)&g,   g_g);
    cudaGetSymbolAddress((void**)&u,   g_u);

    cudaFuncSetAttribute(attn_kernel, cudaFuncAttributeMaxDynamicSharedMemorySize, ATTN_SMEM);
    cudaFuncSetAttribute(gemm_kernel, cudaFuncAttributeMaxDynamicSharedMemorySize, GEMM_SMEM);
    cudaFuncSetAttribute(qkv_kernel,  cudaFuncAttributeMaxDynamicSharedMemorySize, GEMM_SMEM);
    cudaFuncSetAttribute(gu_kernel,   cudaFuncAttributeMaxDynamicSharedMemorySize, GEMM_SMEM);

    // 1) rmsnorm1
    rmsnorm_kernel<<<ROWS, 256>>>(x, ln1, h);
    // 2) fused qkv projections
    qkv_kernel<<<dim3(12, ROWS/128), 128, GEMM_SMEM>>>(h, wq, wk, wv, q, k, v);
    // 3) rope
    {
        int t = ROWS * (NQH + NKVH) * 64;
        rope_kernel<<<(t + 255) / 256, 256>>>(q, k, t);
    }
    // 4) attention (fp16 wmma, 2 CTAs/SM)
    attn_kernel<<<dim3(LL / TQ, NQH, BB), 256, ATTN_SMEM>>>(q, k, v, ctx);
    // 5) output proj + residual
    gemm_kernel<<<dim3(DD/128, ROWS/128), 128, GEMM_SMEM>>>(ctx, wo, x, x1, DD, DD);
    // 6) rmsnorm2
    rmsnorm_kernel<<<ROWS, 256>>>(x1, ln2, h2);
    // 7) fused ffn gate+up
    gu_kernel<<<dim3(64, ROWS/128), 128, GEMM_SMEM>>>(h2, wg, wu, g, u);
    // 8) silu*mul
    {
        int n4 = ROWS * FFND / 4;
        silu_mul_kernel<<<(n4 + 255) / 256, 256>>>(g, u, g, n4);
    }
    // 9) down proj + residual -> out
    gemm_kernel<<<dim3(DD/128, ROWS/128), 128, GEMM_SMEM>>>(g, wd, x1, out, FFND, DD);
}

// round 8
// speedup vs baseline: 7.9523x; 2.7714x over previous
#include <cuda_runtime.h>
#include <cuda_fp16.h>
#include <mma.h>
#include <math.h>
#include <cstdint>

using namespace nvcuda;

// Problem constants
#define BB 2
#define LL 2048
#define DD 1024
#define NQH 8
#define NKVH 2
#define HD 128
#define FFND 4096
#define ROWS (BB*LL)            // 4096
#define EPSV 1.1920929e-07f

// ---------------- scratch (device globals; no allocs allowed) ----------------
__device__ half  g_h  [ROWS*DD];        // rmsnorm1 out (fp16)
__device__ float g_q  [ROWS*NQH*HD];
__device__ float g_k  [ROWS*NKVH*HD];
__device__ float g_v  [ROWS*NKVH*HD];
__device__ half  g_ctx[ROWS*DD];        // attention out (fp16)
__device__ float g_x1 [ROWS*DD];        // post-attn residual (fp32)
__device__ half  g_h2 [ROWS*DD];        // rmsnorm2 out (fp16)
__device__ float g_g  [ROWS*FFND];
__device__ float g_u  [ROWS*FFND];
__device__ half  g_act[ROWS*FFND];      // silu*u (fp16)
// fp16 weight copies
__device__ half  g_wqh[DD*NQH*HD];
__device__ half  g_wkh[DD*NKVH*HD];
__device__ half  g_wvh[DD*NKVH*HD];
__device__ half  g_woh[DD*DD];
__device__ half  g_wgh[DD*FFND];
__device__ half  g_wuh[DD*FFND];
__device__ half  g_wdh[FFND*DD];

// ---------------- pack helpers ----------------
union HPack { half2 h[2]; uint2 u; };
__device__ __forceinline__ uint2 pack4(float a, float b, float c, float d) {
    HPack p;
    p.h[0] = __floats2half2_rn(a, b);
    p.h[1] = __floats2half2_rn(c, d);
    return p.u;
}

// ---------------- fused weight fp32->fp16 conversion (one launch) ----------------
#define N4_WQ 262144
#define N4_WK 65536
#define N4_WV 65536
#define N4_WO 262144
#define N4_WG 1048576
#define N4_WU 1048576
#define N4_WD 1048576
#define N4_TOT (N4_WQ+N4_WK+N4_WV+N4_WO+N4_WG+N4_WU+N4_WD)   // 3801088

__global__ void convert_weights_kernel(
    const float* __restrict__ wq, const float* __restrict__ wk, const float* __restrict__ wv,
    const float* __restrict__ wo, const float* __restrict__ wg, const float* __restrict__ wu,
    const float* __restrict__ wd,
    half* __restrict__ wqh, half* __restrict__ wkh, half* __restrict__ wvh,
    half* __restrict__ woh, half* __restrict__ wgh, half* __restrict__ wuh,
    half* __restrict__ wdh)
{
    int i = blockIdx.x * blockDim.x + threadIdx.x;
    if (i >= N4_TOT) return;
    const float* src; half* dst; int off = i;
    if      (off < N4_WQ)                         { src = wq; dst = wqh; }
    else if ((off -= N4_WQ) < N4_WK)              { src = wk; dst = wkh; }
    else if ((off -= N4_WK) < N4_WV)              { src = wv; dst = wvh; }
    else if ((off -= N4_WV) < N4_WO)              { src = wo; dst = woh; }
    else if ((off -= N4_WO) < N4_WG)              { src = wg; dst = wgh; }
    else if ((off -= N4_WG) < N4_WU)              { src = wu; dst = wuh; }
    else    { off -= N4_WU;                         src = wd; dst = wdh; }
    float4 v = ((const float4*)src)[off];
    ((uint2*)dst)[off] = pack4(v.x, v.y, v.z, v.w);
}

// ---------------- RMSNorm (fp32 in, fp16 out) ----------------
__global__ __launch_bounds__(256) void rmsnorm_kernel(
    const float* __restrict__ x, const float* __restrict__ w, half* __restrict__ out)
{
    int row = blockIdx.x;
    const float4* xr = (const float4*)(x + (size_t)row * DD);
    float4 v = xr[threadIdx.x];
    float s = v.x*v.x + v.y*v.y + v.z*v.z + v.w*v.w;
    #pragma unroll
    for (int off = 16; off; off >>= 1) s += __shfl_xor_sync(0xffffffffu, s, off);
    __shared__ float red[8];
    if ((threadIdx.x & 31) == 0) red[threadIdx.x >> 5] = s;
    __syncthreads();
    float tot = red[0]+red[1]+red[2]+red[3]+red[4]+red[5]+red[6]+red[7];
    float r = rsqrtf(tot * (1.0f/DD) + EPSV);
    const float4 wv = ((const float4*)w)[threadIdx.x];
    ((uint2*)(out + (size_t)row * DD))[threadIdx.x] =
        pack4(v.x*r*wv.x, v.y*r*wv.y, v.z*r*wv.z, v.w*r*wv.w);
}

// ---------------- RoPE (in-place, q+k in one launch) ----------------
__global__ void rope_kernel(float* __restrict__ q, float* __restrict__ k, int total)
{
    int idx = blockIdx.x * blockDim.x + threadIdx.x;
    if (idx >= total) return;
    int d = idx & 63;
    int t = idx >> 6;
    int hh = t % (NQH + NKVH);
    int row = t / (NQH + NKVH);
    int pos = row & (LL - 1);
    float freq = powf(10000.0f, (float)d * (2.0f / HD));
    float rad = (float)pos / freq;
    float sn, cs;
    sincosf(rad, &sn, &cs);
    float* p = (hh < NQH) ? (q + ((size_t)row * NQH + hh) * HD)
                          : (k + ((size_t)row * NKVH + (hh - NQH)) * HD);
    float x1 = p[d], x2 = p[d + 64];
    p[d]      = x1*cs - x2*sn;
    p[d + 64] = x2*cs + x1*sn;
}

// ---------------- fp16 tensor-core GEMM core ----------------
// Block tile 128x128x64, 2-stage cp.async, 4 warps (64x64 warp tile), m16n16k16
#define APH 72                  // A pitch (halves)
#define BPH 136                 // B pitch (halves)
#define HASZ (128*APH)          // 9216 halves
#define HBSZ (64*BPH)           // 8704 halves
#define HSTG (HASZ + HBSZ)      // 17920 halves per stage
#define GEMM_SMEM (2*HSTG*2)    // 71680 bytes

__device__ __forceinline__ void cp_async16h(half* smem, const half* g)
{
    unsigned int s = (unsigned int)__cvta_generic_to_shared(smem);
    asm volatile("cp.async.cg.shared.global [%0], [%1], 16;\n" :: "r"(s), "l"(g));
}

__device__ __forceinline__ void gemm_stage_load(
    half* As, half* Bs, const half* A, const half* B,
    int K, int ldb, int bm0, int col0, int k0, int tid)
{
    #pragma unroll
    for (int p = 0; p < 8; p++) {
        int idx = p * 128 + tid;
        int row = idx >> 3, c8 = (idx & 7) * 8;
        cp_async16h(As + row*APH + c8, A + (size_t)(bm0 + row)*K + k0 + c8);
    }
    #pragma unroll
    for (int p = 0; p < 8; p++) {
        int idx = p * 128 + tid;
        int br = idx >> 4, bc8 = (idx & 15) * 8;
        cp_async16h(Bs + br*BPH + bc8, B + (size_t)(k0 + br)*ldb + col0 + bc8);
    }
    asm volatile("cp.async.commit_group;\n" ::);
}

__device__ __forceinline__ void gemm_core(
    const half* __restrict__ A, const half* __restrict__ B,
    const float* __restrict__ Res, float* __restrict__ C,
    int K, int ldb, int ldc, int bm0, int col0)
{
    extern __shared__ half smh[];
    int tid  = threadIdx.x;
    int warp = tid >> 5;
    int wm = warp & 1;
    int wn = warp >> 1;

    wmma::fragment<wmma::accumulator, 16,16,16, float> acc[4][4];
    #pragma unroll
    for (int i = 0; i < 4; i++)
        #pragma unroll
        for (int j = 0; j < 4; j++)
            wmma::fill_fragment(acc[i][j], 0.0f);

    int nk = K >> 6;

    gemm_stage_load(smh, smh + HASZ, A, B, K, ldb, bm0, col0, 0, tid);

    for (int kt = 0; kt < nk; kt++) {
        asm volatile("cp.async.wait_group 0;\n" ::);
        __syncthreads();

        if (kt + 1 < nk) {
            int s = (kt + 1) & 1;
            gemm_stage_load(smh + s*HSTG, smh + s*HSTG + HASZ, A, B, K, ldb, bm0, col0, (kt + 1) << 6, tid);
        }

        half* As = smh + (kt & 1) * HSTG;
        half* Bs = As + HASZ;
        #pragma unroll
        for (int ks = 0; ks < 4; ks++) {
            wmma::fragment<wmma::matrix_a, 16,16,16, half, wmma::row_major> af[4];
            wmma::fragment<wmma::matrix_b, 16,16,16, half, wmma::row_major> bf[4];
            #pragma unroll
            for (int i = 0; i < 4; i++)
                wmma::load_matrix_sync(af[i], As + (wm*64 + i*16)*APH + ks*16, APH);
            #pragma unroll
            for (int j = 0; j < 4; j++)
                wmma::load_matrix_sync(bf[j], Bs + (ks*16)*BPH + wn*64 + j*16, BPH);
            #pragma unroll
            for (int i = 0; i < 4; i++)
                #pragma unroll
                for (int j = 0; j < 4; j++)
                    wmma::mma_sync(acc[i][j], af[i], bf[j], acc[i][j]);
        }
    }

    // epilogue (+ optional residual), fp32 out
    #pragma unroll
    for (int i = 0; i < 4; i++) {
        int r0 = bm0 + wm*64 + i*16;
        #pragma unroll
        for (int j = 0; j < 4; j++) {
            int c0 = col0 + wn*64 + j*16;
            if (Res) {
                wmma::fragment<wmma::accumulator, 16,16,16, float> rf;
                wmma::load_matrix_sync(rf, Res + (size_t)r0*ldc + c0, ldc, wmma::mem_row_major);
                #pragma unroll
                for (int e = 0; e < rf.num_elements; e++)
                    acc[i][j].x[e] += rf.x[e];
            }
            wmma::store_matrix_sync(C + (size_t)r0*ldc + c0, acc[i][j], ldc, wmma::mem_row_major);
        }
    }
}

__global__ __launch_bounds__(128) void gemm_kernel(
    const half* __restrict__ A, const half* __restrict__ B,
    const float* __restrict__ Res, float* __restrict__ C, int K, int N)
{
    gemm_core(A, B, Res, C, K, N, N, blockIdx.y * 128, blockIdx.x * 128);
}

__global__ __launch_bounds__(128) void qkv_kernel(
    const half* __restrict__ h,
    const half* __restrict__ wq, const half* __restrict__ wk, const half* __restrict__ wv,
    float* __restrict__ q, float* __restrict__ k, float* __restrict__ v)
{
    int bn = blockIdx.x;
    const half* B; float* C; int ldn; int c0;
    if (bn < 8)       { B = wq; C = q; ldn = NQH*HD;  c0 = bn * 128; }
    else if (bn < 10) { B = wk; C = k; ldn = NKVH*HD; c0 = (bn - 8) * 128; }
    else              { B = wv; C = v; ldn = NKVH*HD; c0 = (bn - 10) * 128; }
    gemm_core(h, B, nullptr, C, DD, ldn, ldn, blockIdx.y * 128, c0);
}

__global__ __launch_bounds__(128) void gu_kernel(
    const half* __restrict__ h2,
    const half* __restrict__ wg, const half* __restrict__ wu,
    float* __restrict__ g, float* __restrict__ u)
{
    int bn = blockIdx.x;
    const half* B = (bn < 32) ? wg : wu;
    float* C      = (bn < 32) ? g  : u;
    int c0 = (bn & 31) * 128;
    gemm_core(h2, B, nullptr, C, DD, FFND, FFND, blockIdx.y * 128, c0);
}

// ---------------- Flash attention: fp16 wmma, fp32 softmax, fp16 ctx out ----------------
#define TQ 64
#define TK 64
#define HP 136
#define SP 72
#define PP 80
#define OP 132
#define ATTN_SMEM (3*TQ*HP*2 + TQ*SP*4 + TQ*PP*2 + TQ*OP*4)   // 114688 bytes

__global__ __launch_bounds__(256, 2) void attn_kernel(
    const float* __restrict__ Q, const float* __restrict__ K,
    const float* __restrict__ V, half* __restrict__ O)
{
    extern __shared__ char smraw[];
    half*  hQ = (half*)smraw;
    half*  hK = hQ + TQ * HP;
    half*  hV = hK + TQ * HP;
    float* sS = (float*)(hV + TQ * HP);
    half*  sP = (half*)(sS + TQ * SP);
    float* sO = (float*)(sP + TQ * PP);

    int qt = (gridDim.x - 1) - blockIdx.x;
    int h = blockIdx.y, b = blockIdx.z;
    int kh = h >> 2;
    int tid = threadIdx.x;
    int warp = tid >> 5, lane = tid & 31;
    int q0 = qt * TQ;
    int wr = warp & 1, wc = warp >> 1;

    #pragma unroll
    for (int it = 0; it < (TQ * HD / 4) / 256; it++) {
        int idx = it * 256 + tid;
        int r = idx >> 5, c4 = idx & 31;
        float4 v = *(const float4*)(Q + ((size_t)((b*LL + q0 + r)*NQH + h))*HD + c4*4);
        *(uint2*)(hQ + r * HP + c4 * 4) = pack4(v.x, v.y, v.z, v.w);
    }

    float o[8][4], m[8], l[8];
    #pragma unroll
    for (int r = 0; r < 8; r++) {
        m[r] = -1e30f; l[r] = 0.f;
        o[r][0] = o[r][1] = o[r][2] = o[r][3] = 0.f;
    }
    const float scale = 0.08838834764831845f;

    for (int kt = 0; kt <= qt; kt++) {
        int kb = kt * TK;
        __syncthreads();   // A
        #pragma unroll
        for (int it = 0; it < (TK * HD / 4) / 256; it++) {
            int idx = it * 256 + tid;
            int j = idx >> 5, c4 = idx & 31;
            float4 kv = *(const float4*)(K + ((size_t)((b*LL + kb + j)*NKVH + kh))*HD + c4*4);
            *(uint2*)(hK + j * HP + c4*4) = pack4(kv.x, kv.y, kv.z, kv.w);
            float4 vv = *(const float4*)(V + ((size_t)((b*LL + kb + j)*NKVH + kh))*HD + c4*4);
            *(uint2*)(hV + j * HP + c4*4) = pack4(vv.x, vv.y, vv.z, vv.w);
        }
        __syncthreads();   // B

        {
            wmma::fragment<wmma::accumulator, 16,16,16, float> sacc[2];
            wmma::fill_fragment(sacc[0], 0.0f);
            wmma::fill_fragment(sacc[1], 0.0f);
            #pragma unroll
            for (int kk = 0; kk < 8; kk++) {
                wmma::fragment<wmma::matrix_b, 16,16,16, half, wmma::col_major> bf;
                wmma::load_matrix_sync(bf, hK + (wc*16)*HP + kk*16, HP);
                #pragma unroll
                for (int i = 0; i < 2; i++) {
                    wmma::fragment<wmma::matrix_a, 16,16,16, half, wmma::row_major> af;
                    wmma::load_matrix_sync(af, hQ + (wr*32 + i*16)*HP + kk*16, HP);
                    wmma::mma_sync(sacc[i], af, bf, sacc[i]);
                }
            }
            wmma::store_matrix_sync(sS + (wr*32 +  0)*SP + wc*16, sacc[0], SP, wmma::mem_row_major);
            wmma::store_matrix_sync(sS + (wr*32 + 16)*SP + wc*16, sacc[1], SP, wmma::mem_row_major);
        }
        __syncthreads();   // C

        #pragma unroll
        for (int rr = 0; rr < 8; rr++) {
            int row = warp*8 + rr;
            int qi = q0 + row;
            float s1 = sS[row*SP + lane];
            float s2 = sS[row*SP + lane + 32];
            s1 = (kb + lane      <= qi) ? s1 * scale : -1e30f;
            s2 = (kb + lane + 32 <= qi) ? s2 * scale : -1e30f;
            float mx = fmaxf(s1, s2);
            #pragma unroll
            for (int off = 16; off; off >>= 1)
                mx = fmaxf(mx, __shfl_xor_sync(0xffffffffu, mx, off));
            float mnew = fmaxf(m[rr], mx);
            float p1 = __expf(s1 - mnew);
            float p2 = __expf(s2 - mnew);
            float ps = p1 + p2;
            #pragma unroll
            for (int off = 16; off; off >>= 1)
                ps += __shfl_xor_sync(0xffffffffu, ps, off);
            float alpha = __expf(m[rr] - mnew);
            m[rr] = mnew;
            l[rr] = l[rr] * alpha + ps;
            o[rr][0] *= alpha; o[rr][1] *= alpha; o[rr][2] *= alpha; o[rr][3] *= alpha;
            sP[row*PP + lane]      = __float2half(p1);
            sP[row*PP + lane + 32] = __float2half(p2);
        }
        __syncthreads();   // D

        {
            wmma::fragment<wmma::accumulator, 16,16,16, float> pacc[2][2];
            #pragma unroll
            for (int i = 0; i < 2; i++)
                #pragma unroll
                for (int j = 0; j < 2; j++)
                    wmma::fill_fragment(pacc[i][j], 0.0f);
            #pragma unroll
            for (int kk = 0; kk < 4; kk++) {
                wmma::fragment<wmma::matrix_a, 16,16,16, half, wmma::row_major> af[2];
                wmma::fragment<wmma::matrix_b, 16,16,16, half, wmma::row_major> bf[2];
                #pragma unroll
                for (int i = 0; i < 2; i++)
                    wmma::load_matrix_sync(af[i], sP + (wr*32 + i*16)*PP + kk*16, PP);
                #pragma unroll
                for (int j = 0; j < 2; j++)
                    wmma::load_matrix_sync(bf[j], hV + (kk*16)*HP + wc*32 + j*16, HP);
                #pragma unroll
                for (int i = 0; i < 2; i++)
                    #pragma unroll
                    for (int j = 0; j < 2; j++)
                        wmma::mma_sync(pacc[i][j], af[i], bf[j], pacc[i][j]);
            }
            #pragma unroll
            for (int i = 0; i < 2; i++)
                #pragma unroll
                for (int j = 0; j < 2; j++)
                    wmma::store_matrix_sync(sO + (wr*32 + i*16)*OP + wc*32 + j*16,
                                            pacc[i][j], OP, wmma::mem_row_major);
        }
        __syncthreads();   // E

        #pragma unroll
        for (int rr = 0; rr < 8; rr++) {
            int row = warp*8 + rr;
            float4 pv = *(const float4*)(sO + row*OP + lane*4);
            o[rr][0] += pv.x; o[rr][1] += pv.y; o[rr][2] += pv.z; o[rr][3] += pv.w;
        }
    }

    #pragma unroll
    for (int rr = 0; rr < 8; rr++) {
        int qi = q0 + warp*8 + rr;
        float inv = 1.0f / l[rr];
        *(uint2*)(O + ((size_t)((b*LL + qi)*NQH + h))*HD + lane*4) =
            pack4(o[rr][0]*inv, o[rr][1]*inv, o[rr][2]*inv, o[rr][3]*inv);
    }
}

// ---------------- silu(g) * u -> fp16 ----------------
__global__ void silu_mul_kernel(const float* __restrict__ g, const float* __restrict__ u,
                                half* __restrict__ out, int n4)
{
    int i = blockIdx.x * blockDim.x + threadIdx.x;
    if (i >= n4) return;
    float4 gv = ((const float4*)g)[i];
    float4 uv = ((const float4*)u)[i];
    ((uint2*)out)[i] = pack4(
        gv.x / (1.f + __expf(-gv.x)) * uv.x,
        gv.y / (1.f + __expf(-gv.y)) * uv.y,
        gv.z / (1.f + __expf(-gv.z)) * uv.z,
        gv.w / (1.f + __expf(-gv.w)) * uv.w);
}

// ---------------- launch ----------------
extern "C" void kernel_launch(void* const* d_in, const int* in_sizes, int n_in,
                              void* d_out, int out_size)
{
    const float* x   = (const float*)d_in[0];
    const float* ln1 = (const float*)d_in[1];
    const float* wq  = (const float*)d_in[2];
    const float* wk  = (const float*)d_in[3];
    const float* wv  = (const float*)d_in[4];
    const float* wo  = (const float*)d_in[5];
    const float* ln2 = (const float*)d_in[6];
    const float* wg  = (const float*)d_in[7];
    const float* wu  = (const float*)d_in[8];
    const float* wd  = (const float*)d_in[9];
    float* out = (float*)d_out;

    half *h, *ctx, *h2, *act;
    float *q, *k, *v, *x1, *g, *u;
    half *wqh, *wkh, *wvh, *woh, *wgh, *wuh, *wdh;
    cudaGetSymbolAddress((void**)&h,   g_h);
    cudaGetSymbolAddress((void**)&q,   g_q);
    cudaGetSymbolAddress((void**)&k,   g_k);
    cudaGetSymbolAddress((void**)&v,   g_v);
    cudaGetSymbolAddress((void**)&ctx, g_ctx);
    cudaGetSymbolAddress((void**)&x1,  g_x1);
    cudaGetSymbolAddress((void**)&h2,  g_h2);
    cudaGetSymbolAddress((void**)&g,   g_g);
    cudaGetSymbolAddress((void**)&u,   g_u);
    cudaGetSymbolAddress((void**)&act, g_act);
    cudaGetSymbolAddress((void**)&wqh, g_wqh);
    cudaGetSymbolAddress((void**)&wkh, g_wkh);
    cudaGetSymbolAddress((void**)&wvh, g_wvh);
    cudaGetSymbolAddress((void**)&woh, g_woh);
    cudaGetSymbolAddress((void**)&wgh, g_wgh);
    cudaGetSymbolAddress((void**)&wuh, g_wuh);
    cudaGetSymbolAddress((void**)&wdh, g_wdh);

    cudaFuncSetAttribute(attn_kernel, cudaFuncAttributeMaxDynamicSharedMemorySize, ATTN_SMEM);
    cudaFuncSetAttribute(gemm_kernel, cudaFuncAttributeMaxDynamicSharedMemorySize, GEMM_SMEM);
    cudaFuncSetAttribute(qkv_kernel,  cudaFuncAttributeMaxDynamicSharedMemorySize, GEMM_SMEM);
    cudaFuncSetAttribute(gu_kernel,   cudaFuncAttributeMaxDynamicSharedMemorySize, GEMM_SMEM);

    // 0) weights -> fp16 (single launch)
    convert_weights_kernel<<<(N4_TOT + 255) / 256, 256>>>(
        wq, wk, wv, wo, wg, wu, wd, wqh, wkh, wvh, woh, wgh, wuh, wdh);
    // 1) rmsnorm1 -> fp16
    rmsnorm_kernel<<<ROWS, 256>>>(x, ln1, h);
    // 2) fused qkv projections (fp16 gemm)
    qkv_kernel<<<dim3(12, ROWS/128), 128, GEMM_SMEM>>>(h, wqh, wkh, wvh, q, k, v);
    // 3) rope
    {
        int t = ROWS * (NQH + NKVH) * 64;
        rope_kernel<<<(t + 255) / 256, 256>>>(q, k, t);
    }
    // 4) attention -> fp16 ctx
    attn_kernel<<<dim3(LL / TQ, NQH, BB), 256, ATTN_SMEM>>>(q, k, v, ctx);
    // 5) output proj + residual (ncu -s 5 lands here)
    gemm_kernel<<<dim3(DD/128, ROWS/128), 128, GEMM_SMEM>>>(ctx, woh, x, x1, DD, DD);
    // 6) rmsnorm2 -> fp16
    rmsnorm_kernel<<<ROWS, 256>>>(x1, ln2, h2);
    // 7) fused ffn gate+up
    gu_kernel<<<dim3(64, ROWS/128), 128, GEMM_SMEM>>>(h2, wgh, wuh, g, u);
    // 8) silu*mul -> fp16
    {
        int n4 = ROWS * FFND / 4;
        silu_mul_kernel<<<(n4 + 255) / 256, 256>>>(g, u, act, n4);
    }
    // 9) down proj + residual -> out
    gemm_kernel<<<dim3(DD/128, ROWS/128), 128, GEMM_SMEM>>>(act, wdh, x1, out, FFND, DD);
}